// round 10
// baseline (speedup 1.0000x reference)
#include <cuda_runtime.h>

#define BATCH 4
#define NP 30000
#define BN (BATCH*NP)
#define HID 64
#define FD 256
#define R2 4096
#define NT 469   /* ceil(NP/64) */
#define NBROW (3*BATCH*R2)

// ---------------- scratch (no allocation allowed) ----------------
__device__ float g_net[BN*HID];
__device__ int   g_idx[3*BN];
__device__ float g_binsum2[2*BATCH*R2*HID];
__device__ float g_bincnt2[2*BATCH*R2];
__device__ float g_nsum[NBROW*HID];
__device__ float g_cnt3[NBROW];
__device__ __align__(128) float g_fea[NBROW*FD];     // conv1 in  (permuted tf32)
__device__ __align__(128) float g_feb[NBROW*FD];     // conv1 out (permuted tf32)
__device__ __align__(128) float g_fec[NBROW*FD];     // conv2 out (natural fp32)
__device__ __align__(128) float g_wt[2*2304*FD];     // conv tf32 wt [conv][ch][kk][ocb4][512 pair-interleaved]
__device__ __align__(128) float g_wblk[3*20480];     // resblock tf32 wt (pair-interleaved)
__device__ __align__(128) float g_wfcc[16384];       // fc_c tf32 wt [8kc][256n][8s]

// ---------------- helpers ----------------
__device__ __forceinline__ float totf(float x){
    unsigned u; asm("cvt.rna.tf32.f32 %0, %1;" : "=r"(u) : "f"(x));
    return __uint_as_float(u);
}
__device__ __forceinline__ void cpa(unsigned d, const void* s, int sz){
    asm volatile("cp.async.cg.shared.global [%0], [%1], 16, %2;" :: "r"(d), "l"(s), "r"(sz));
}
#define CP_COMMIT asm volatile("cp.async.commit_group;")
#define CP_WAIT0  asm volatile("cp.async.wait_group 0;")

__device__ __forceinline__ void mma8(float* d, uint2 ar0, uint2 ar1, uint2 b){
    asm volatile("mma.sync.aligned.m16n8k8.row.col.f32.tf32.tf32.f32 "
        "{%0,%1,%2,%3}, {%4,%5,%6,%7}, {%8,%9}, {%0,%1,%2,%3};"
        : "+f"(d[0]),"+f"(d[1]),"+f"(d[2]),"+f"(d[3])
        : "r"(ar0.x),"r"(ar1.x),"r"(ar0.y),"r"(ar1.y), "r"(b.x),"r"(b.y));
}
// A fragment delivered directly in (a0,a1,a2,a3) order by one LDS.128
__device__ __forceinline__ void mma8v(float* d, uint4 a, unsigned b0, unsigned b1){
    asm volatile("mma.sync.aligned.m16n8k8.row.col.f32.tf32.tf32.f32 "
        "{%0,%1,%2,%3}, {%4,%5,%6,%7}, {%8,%9}, {%0,%1,%2,%3};"
        : "+f"(d[0]),"+f"(d[1]),"+f"(d[2]),"+f"(d[3])
        : "r"(a.x),"r"(a.y),"r"(a.z),"r"(a.w), "r"(b0),"r"(b1));
}

// ---------------- bin indices ----------------
__device__ __forceinline__ int binof(float v){
    const float DEN = (float)(1.0 + 0.1 + 1e-6);
    float w = (v + 0.5f) / DEN;
    w = fminf(fmaxf(w, 0.0f), (float)(1.0 - 1e-6));
    return (int)(w * 64.0f);
}

__global__ void k_idx(const float* __restrict__ p){
    int i = blockIdx.x*256 + threadIdx.x;
    if(i >= BN) return;
    float x = p[i*3+0], y = p[i*3+1], z = p[i*3+2];
    int bx = binof(x), by = binof(y), bz = binof(z);
    g_idx[0*BN+i] = bx + 64*bz;
    g_idx[1*BN+i] = bx + 64*by;
    g_idx[2*BN+i] = by + 64*bz;
}

// ---------------- resblock weight prep: pair-interleaved ----------------
// per mode: [0,8192) W0 [16kc][512]; [8192,12288) W1 [8kc][512]; [12288,20480) Ws [16kc][512]
// within 512: e = wn*256 + ntp*128 + qn*16 + s*2 + g ; n = wn*32+ntp*16+g*8+qn ; k = kc*8+(s&1)*4+(s>>1)
__global__ void k_wblk(const float* __restrict__ W0, const float* __restrict__ W1,
                       const float* __restrict__ Ws){
    int i = blockIdx.x*256 + threadIdx.x;
    if(i >= 3*20480) return;
    int m = i / 20480, r = i - m*20480;
    const float* src; int kc, e, K;
    if(r < 8192){ src = W0 + m*64*128; kc = r>>9; e = r&511; K = 128; }
    else if(r < 12288){ int q = r-8192; src = W1 + m*64*64; kc = q>>9; e = q&511; K = 64; }
    else { int q = r-12288; src = Ws + m*64*128; kc = q>>9; e = q&511; K = 128; }
    int wn = e>>8, ntp = (e>>7)&1, qn = (e>>4)&7, s = (e>>1)&7, g = e&1;
    int n = wn*32 + ntp*16 + g*8 + qn;
    int k = kc*8 + (s&1)*4 + (s>>1);
    g_wblk[i] = totf(src[n*K + k]);
}

// ---------------- fc_c weight prep ----------------
__global__ void k_wfcc(const float* __restrict__ Wc){
    int i = blockIdx.x*256 + threadIdx.x;
    if(i >= 16384) return;
    int s = i & 7, n = (i>>3)&255, kc = i>>11;
    int k = kc*8 + (s&1)*4 + (s>>1);
    g_wfcc[i] = totf(Wc[n*64 + k]);
}

// ---------------- fused resblock + scatter epilogue, TF32 mma, 2 CTA/SM, LDS.128 frags ----------------
// x_s: [kc][rg4][qp8][s8][grp2]  (pt = rg*16 + grp*8 + qp); h aliases first 8 kc
#define SM_BLOCK ((8192 + 16384)*4)

__global__ void __launch_bounds__(256, 2) k_block(int mode, const float* __restrict__ p,
                        const float* __restrict__ fcW, const float* __restrict__ fcb,
                        const float* __restrict__ b0g, const float* __restrict__ b1g)
{
    extern __shared__ float sm[];
    float* x_s  = sm;              // 8192 floats
    float* wA   = sm + 8192;       // w0 then w1
    float* ws_s = sm + 16384;      // ws
    unsigned wA_u = (unsigned)__cvta_generic_to_shared(wA);

    int t = threadIdx.x;
    int lane = t & 31, w = t >> 5;
    int wm = w & 3, wn = w >> 2;
    int q = lane >> 2, c = lane & 3;
    int s0 = (c < 2) ? 4*c     : 4*c - 7;   // slot of k=2c
    int s1 = (c < 2) ? 4*c + 2 : 4*c - 5;   // slot of k=2c+1

    int b = blockIdx.x / NT, tile = blockIdx.x % NT;
    int pt0 = tile*64;
    int npts = min(64, NP - pt0);
    int gbase = b*NP + pt0;

    // stage w0 + ws (flat copy; layouts match)
    {
        const float* wsrc = g_wblk + mode*20480;
        for(int e=t; e<4096; e+=256){
            const float* src = (e < 2048) ? (wsrc + e*4) : (wsrc + 12288 + (e-2048)*4);
            cpa(wA_u + (unsigned)e*16, src, 16);
        }
        CP_COMMIT;
    }

    // stage x tile (interleaved): value (pt, slot 2*i2+half) at kc*512+rg*128+qp*16+(2*i2+half)*2+grp
    if(mode == 0){
        for(int e=t; e<2048; e+=256){
            int pt = e>>5, gg = e&31;
            int kc = gg>>1, half = gg&1;
            int kb = kc*8 + half*4;
            float* d = &x_s[kc*512 + (pt>>4)*128 + (pt&7)*16 + ((pt>>3)&1) + half*2];
            if(pt < npts){
                int gp = (gbase + pt)*3;
                float px = p[gp], py = p[gp+1], pz = p[gp+2];
                #pragma unroll
                for(int i2=0;i2<4;i2++){
                    int j = kb + i2;
                    float v = fcb[j] + px*fcW[j*3] + py*fcW[j*3+1] + pz*fcW[j*3+2];
                    d[4*i2] = totf(v);
                }
            } else {
                d[0]=0.f; d[4]=0.f; d[8]=0.f; d[12]=0.f;
            }
        }
    } else {
        const float* bs   = g_binsum2 + ((mode-1)&1)*(BATCH*R2*HID);
        const float* bcnt = g_bincnt2 + ((mode-1)&1)*(BATCH*R2);
        for(int e=t; e<2048; e+=256){
            int pt = e>>5, gg = e&31;
            int kc = gg>>1, half = gg&1;
            float4 v = make_float4(0.f,0.f,0.f,0.f);
            if(pt < npts){
                int gi = gbase + pt;
                if(kc < 8) v = *(const float4*)&g_net[gi*HID + kc*8 + half*4];
                else {
                    int row = b*R2 + g_idx[gi];
                    float inv = 1.0f / fmaxf(bcnt[row], 1.0f);
                    v = *(const float4*)&bs[row*HID + (kc-8)*8 + half*4];
                    v.x*=inv; v.y*=inv; v.z*=inv; v.w*=inv;
                }
            }
            float* d = &x_s[kc*512 + (pt>>4)*128 + (pt&7)*16 + ((pt>>3)&1) + half*2];
            d[0]=totf(v.x); d[4]=totf(v.y); d[8]=totf(v.z); d[12]=totf(v.w);
        }
    }
    CP_WAIT0;
    __syncthreads();

    int rb = wm*16;
    int r0 = rb + q, r1 = rb + q + 8;
    int abase = wm*128 + q*16 + 4*c;
    int bbase = wn*256 + q*16 + 4*c;

    // PASS 1 (fused): aH = x@W0^T ; aS = x@Ws^T
    float aH[4][4], aS[4][4];
    #pragma unroll
    for(int nt=0;nt<4;nt++){
        aH[nt][0]=aH[nt][1]=aH[nt][2]=aH[nt][3]=0.f;
        aS[nt][0]=aS[nt][1]=aS[nt][2]=aS[nt][3]=0.f;
    }
    #pragma unroll 4
    for(int kc=0; kc<16; kc++){
        uint4 av = *(const uint4*)&x_s[kc*512 + abase];
        #pragma unroll
        for(int ntp=0; ntp<2; ntp++){
            uint4 w0v = *(const uint4*)&wA  [kc*512 + bbase + ntp*128];
            uint4 wsv = *(const uint4*)&ws_s[kc*512 + bbase + ntp*128];
            mma8v(aH[2*ntp],   av, w0v.x, w0v.z);
            mma8v(aH[2*ntp+1], av, w0v.y, w0v.w);
            mma8v(aS[2*ntp],   av, wsv.x, wsv.z);
            mma8v(aS[2*ntp+1], av, wsv.y, wsv.w);
        }
    }
    __syncthreads();   // x_s and w0 now dead

    // stage w1 over w0; write h into x_s alias (interleaved layout)
    {
        const float* wsrc = g_wblk + mode*20480 + 8192;
        for(int e=t; e<1024; e+=256)
            cpa(wA_u + (unsigned)e*16, wsrc + e*4, 16);
        CP_COMMIT;
    }
    #pragma unroll
    for(int nt=0; nt<4; nt++){
        int j0 = wn*32 + nt*8 + 2*c;
        float2 bb = *(const float2*)&b0g[j0];
        float* dl = &x_s[(j0>>3)*512 + wm*128 + q*16];
        dl[s0*2 + 0] = totf(fmaxf(aH[nt][0]+bb.x, 0.f));   // (r0, k=2c)
        dl[s1*2 + 0] = totf(fmaxf(aH[nt][1]+bb.y, 0.f));   // (r0, k=2c+1)
        dl[s0*2 + 1] = totf(fmaxf(aH[nt][2]+bb.x, 0.f));   // (r1, k=2c)
        dl[s1*2 + 1] = totf(fmaxf(aH[nt][3]+bb.y, 0.f));   // (r1, k=2c+1)
    }
    CP_WAIT0;
    __syncthreads();

    // PASS 2: aD = h @ W1^T
    float aD[4][4];
    #pragma unroll
    for(int nt=0;nt<4;nt++){ aD[nt][0]=aD[nt][1]=aD[nt][2]=aD[nt][3]=0.f; }
    #pragma unroll
    for(int kc=0; kc<8; kc++){
        uint4 av = *(const uint4*)&x_s[kc*512 + abase];
        #pragma unroll
        for(int ntp=0; ntp<2; ntp++){
            uint4 wv = *(const uint4*)&wA[kc*512 + bbase + ntp*128];
            mma8v(aD[2*ntp],   av, wv.x, wv.z);
            mma8v(aD[2*ntp+1], av, wv.y, wv.w);
        }
    }
    #pragma unroll
    for(int nt=0; nt<4; nt++){
        int j0 = wn*32 + nt*8 + 2*c;
        float2 bb = *(const float2*)&b1g[j0];
        aD[nt][0] = fmaxf(aD[nt][0]+bb.x, 0.f) + aS[nt][0];
        aD[nt][1] = fmaxf(aD[nt][1]+bb.y, 0.f) + aS[nt][1];
        aD[nt][2] = fmaxf(aD[nt][2]+bb.x, 0.f) + aS[nt][2];
        aD[nt][3] = fmaxf(aD[nt][3]+bb.y, 0.f) + aS[nt][3];
    }

    // ---------------- epilogue ----------------
    if(mode < 2){
        float* bs   = g_binsum2 + (mode&1)*(BATCH*R2*HID);
        float* bcnt = g_bincnt2 + (mode&1)*(BATCH*R2);
        if(wn==0 && c==0){
            if(r0 < npts) atomicAdd(&bcnt[b*R2 + g_idx[gbase+r0]], 1.0f);
            if(r1 < npts) atomicAdd(&bcnt[b*R2 + g_idx[gbase+r1]], 1.0f);
        }
        int bin0 = (r0 < npts) ? (b*R2 + g_idx[gbase+r0]) : -1;
        int bin1 = (r1 < npts) ? (b*R2 + g_idx[gbase+r1]) : -1;
        #pragma unroll
        for(int nt=0; nt<4; nt++){
            int j0 = wn*32 + nt*8 + 2*c;
            if(bin0 >= 0){
                *(float2*)&g_net[(gbase+r0)*HID + j0] = make_float2(aD[nt][0], aD[nt][1]);
                atomicAdd(&bs[bin0*HID + j0],   aD[nt][0]);
                atomicAdd(&bs[bin0*HID + j0+1], aD[nt][1]);
            }
            if(bin1 >= 0){
                *(float2*)&g_net[(gbase+r1)*HID + j0] = make_float2(aD[nt][2], aD[nt][3]);
                atomicAdd(&bs[bin1*HID + j0],   aD[nt][2]);
                atomicAdd(&bs[bin1*HID + j0+1], aD[nt][3]);
            }
        }
    } else {
        if(wn==0 && c==0){
            #pragma unroll
            for(int hh=0;hh<2;hh++){
                int r = rb + q + hh*8;
                if(r < npts){
                    int gi = gbase + r;
                    #pragma unroll
                    for(int pl=0;pl<3;pl++)
                        atomicAdd(&g_cnt3[(pl*BATCH+b)*R2 + g_idx[pl*BN+gi]], 1.0f);
                }
            }
        }
        int rowp[2][3];
        #pragma unroll
        for(int hh=0;hh<2;hh++){
            int r = rb + q + hh*8;
            if(r < npts){
                int gi = gbase + r;
                #pragma unroll
                for(int pl=0;pl<3;pl++)
                    rowp[hh][pl] = (pl*BATCH+b)*R2 + g_idx[pl*BN+gi];
            } else {
                rowp[hh][0]=rowp[hh][1]=rowp[hh][2]=-1;
            }
        }
        #pragma unroll
        for(int nt=0; nt<4; nt++){
            int j0 = wn*32 + nt*8 + 2*c;
            #pragma unroll
            for(int hh=0;hh<2;hh++){
                if(rowp[hh][0] >= 0){
                    float v0 = aD[nt][hh*2+0], v1 = aD[nt][hh*2+1];
                    #pragma unroll
                    for(int pl=0;pl<3;pl++){
                        atomicAdd(&g_nsum[rowp[hh][pl]*HID + j0],   v0);
                        atomicAdd(&g_nsum[rowp[hh][pl]*HID + j0+1], v1);
                    }
                }
            }
        }
    }
}

// ---------------- bin GEMM fc_c (TF32 mma) ----------------
#define SM_FCC ((4096 + 16384)*4)
__global__ void __launch_bounds__(256) k_fcc_bins(const float* __restrict__ bc){
    extern __shared__ float sm[];
    float* x_s = sm;             // [8kc][64pt][8]
    float* w_s = sm + 4096;      // [8kc][256n][8]
    unsigned ws_u = (unsigned)__cvta_generic_to_shared(w_s);
    int t = threadIdx.x;
    int lane = t & 31, w = t >> 5;
    int wm = w & 1, wn = w >> 1;
    int q = lane >> 2, c = lane & 3;
    int r0b = blockIdx.x*64;

    for(int e=t; e<4096; e+=256)
        cpa(ws_u + (unsigned)e*16, g_wfcc + e*4, 16);
    CP_COMMIT;

    for(int e=t; e<1024; e+=256){
        int pt = e>>4, g = e&15;
        int kc = g>>1, half = g&1;
        int row = r0b + pt;
        float inv = 1.0f / fmaxf(g_cnt3[row], 1.0f);
        float4 v = *(const float4*)&g_nsum[row*HID + kc*8 + half*4];
        float* d = &x_s[kc*512 + pt*8 + half];
        d[0]=totf(v.x*inv); d[2]=totf(v.y*inv); d[4]=totf(v.z*inv); d[6]=totf(v.w*inv);
    }
    CP_WAIT0;
    __syncthreads();

    int rb = wm*32;
    float acc[2][8][4];
    #pragma unroll
    for(int mt=0;mt<2;mt++)
        #pragma unroll
        for(int nt=0;nt<8;nt++){ acc[mt][nt][0]=acc[mt][nt][1]=acc[mt][nt][2]=acc[mt][nt][3]=0.f; }
    #pragma unroll
    for(int kc=0; kc<8; kc++){
        uint2 a[2][2];
        #pragma unroll
        for(int mt=0;mt<2;mt++){
            a[mt][0] = *(const uint2*)&x_s[kc*512 + (rb+mt*16+q)*8 + 2*c];
            a[mt][1] = *(const uint2*)&x_s[kc*512 + (rb+mt*16+q+8)*8 + 2*c];
        }
        const float* wb = &w_s[kc*2048 + (wn*64 + q)*8 + 2*c];
        #pragma unroll
        for(int nt=0; nt<8; nt++){
            uint2 bb = *(const uint2*)&wb[nt*64];
            mma8(acc[0][nt], a[0][0], a[0][1], bb);
            mma8(acc[1][nt], a[1][0], a[1][1], bb);
        }
    }

    const int iperm[8] = {0,2,4,6,1,3,5,7};
    #pragma unroll
    for(int nt=0; nt<8; nt++){
        int j0 = wn*64 + nt*8 + 2*c;
        float2 bb = *(const float2*)&bc[j0];
        #pragma unroll
        for(int mt=0;mt<2;mt++){
            #pragma unroll
            for(int half=0; half<2; half++){
                int r = rb + mt*16 + q + half*8;
                int row = r0b + r;
                float gate = (g_cnt3[row] > 0.f) ? 1.f : 0.f;
                float* d = &g_fea[row*FD + (j0 & ~7)];
                d[iperm[2*c]]   = totf(gate*(acc[mt][nt][half*2+0]+bb.x));
                d[iperm[2*c+1]] = totf(gate*(acc[mt][nt][half*2+1]+bb.y));
            }
        }
    }
}

// ---------------- conv weight prep: [conv][ch][kk][ocb4][512 pair-interleaved] ----------------
__global__ void k_wtrans(const float* __restrict__ Wa, const float* __restrict__ Wb){
    int i = blockIdx.x*256 + threadIdx.x;
    if(i >= 2*2304*FD) return;
    int cI = i / (2304*FD);
    int rem = i - cI*(2304*FD);
    int ch = rem / 18432;
    int r2 = rem - ch*18432;
    int kk = r2 >> 11;                 // r2 / 2048
    int r3 = r2 & 2047;
    int ocb = r3 >> 9;
    int e = r3 & 511;
    int wn = e>>8, ntp = (e>>7)&1, qn = (e>>4)&7, s = (e>>1)&7, g = e&1;
    int oc = ocb*64 + wn*32 + ntp*16 + g*8 + qn;
    int ic = ch*8 + (s&1)*4 + (s>>1);
    const float* W = cI ? Wb : Wa;
    g_wt[i] = totf(W[oc*2304 + ic*9 + kk]);
}

// ---------------- 3x3 conv 256->256, TF32 mma, cp.async, N=64/block, 3 CTA/SM ----------------
#define SM_CONV ((2*2112 + 2*4608)*4)

__global__ void __launch_bounds__(256, 3) k_conv(
        const float* __restrict__ in, float* __restrict__ out,
        const float* __restrict__ wt, const float* __restrict__ bias, int permout)
{
    extern __shared__ float sm[];
    float* ibuf = sm;               // [2][2112]
    float* wbuf = sm + 2*2112;      // [2][9kk][512]
    unsigned ib_u = (unsigned)__cvta_generic_to_shared(ibuf);
    unsigned wb_u = (unsigned)__cvta_generic_to_shared(wbuf);
    int t = threadIdx.x;
    int lane = t & 31, w = t >> 5;
    int wm = w & 3, wn = w >> 2;
    int q = lane >> 2, c = lane & 3;

    int ocb = blockIdx.x & 3;
    int r = blockIdx.x >> 2;
    int rp = r & 31;
    int pb = r >> 5;
    const float* inp  = in  + pb*R2*FD;
    float*       outp = out + pb*R2*FD;
    int y0 = rp*2;
    int px_base = wm*32;
    int bbase = wn*256 + q*16 + 4*c;

    float acc[2][4][4];
    #pragma unroll
    for(int mt=0; mt<2; mt++)
        #pragma unroll
        for(int nt=0; nt<4; nt++){
            acc[mt][nt][0]=0.f; acc[mt][nt][1]=0.f; acc[mt][nt][2]=0.f; acc[mt][nt][3]=0.f;
        }

    auto stage = [&](int ch, int buf){
        for(int e=t; e<528; e+=256){
            int pos = e>>1, half = e&1;
            int rr = pos/66, cc = pos - rr*66;
            int yy = y0 + rr - 1, xx = cc - 1;
            bool ok = (yy >= 0 && yy < 64 && (unsigned)xx < 64u);
            const float* src = inp + ((ok ? (yy*64+xx) : 0)*FD + ch*8 + half*4);
            cpa(ib_u + (unsigned)(buf*2112*4 + pos*32 + half*16), src, ok ? 16 : 0);
        }
        const float* wsrc = wt + (size_t)ch*18432 + ocb*512;
        for(int e=t; e<1152; e+=256){
            int kk = e>>7, rem = e&127;
            cpa(wb_u + (unsigned)(buf*4608*4 + e*16),
                wsrc + kk*2048 + rem*4, 16);
        }
        CP_COMMIT;
    };

    stage(0, 0);
    for(int ch=0; ch<32; ch++){
        int cur = ch & 1;
        CP_WAIT0;
        __syncthreads();
        if(ch < 31) stage(ch+1, 1-cur);
        const float* in_s = ibuf + cur*2112;
        const float* w_s  = wbuf + cur*4608;
        #pragma unroll
        for(int kk=0; kk<9; kk++){
            int ky = kk/3, kx = kk - ky*3;
            uint2 a[2][2];
            #pragma unroll
            for(int mt=0; mt<2; mt++){
                int px0 = px_base + mt*16 + q;
                a[mt][0] = *(const uint2*)&in_s[(((px0>>6)+ky)*66 + (px0&63)+kx)*8 + 2*c];
                int px1 = px0 + 8;
                a[mt][1] = *(const uint2*)&in_s[(((px1>>6)+ky)*66 + (px1&63)+kx)*8 + 2*c];
            }
            const float* wb = &w_s[kk*512 + bbase];
            #pragma unroll
            for(int ntp=0; ntp<2; ntp++){
                uint4 wv = *(const uint4*)&wb[ntp*128];
                uint2 b0 = make_uint2(wv.x, wv.z);
                uint2 b1 = make_uint2(wv.y, wv.w);
                mma8(acc[0][2*ntp],   a[0][0], a[0][1], b0);
                mma8(acc[1][2*ntp],   a[1][0], a[1][1], b0);
                mma8(acc[0][2*ntp+1], a[0][0], a[0][1], b1);
                mma8(acc[1][2*ntp+1], a[1][0], a[1][1], b1);
            }
        }
        __syncthreads();
    }

    int o_base = ocb*64 + wn*32;
    const int iperm[8] = {0,2,4,6,1,3,5,7};
    #pragma unroll
    for(int nt=0; nt<4; nt++){
        int oc = o_base + nt*8 + 2*c;
        float2 bb = *(const float2*)&bias[oc];
        #pragma unroll
        for(int mt=0; mt<2; mt++){
            #pragma unroll
            for(int half=0; half<2; half++){
                int px = px_base + mt*16 + q + half*8;
                int y = y0 + (px>>6), x = px&63;
                float v0 = fmaxf(acc[mt][nt][half*2+0]+bb.x, 0.f);
                float v1 = fmaxf(acc[mt][nt][half*2+1]+bb.y, 0.f);
                float* d = &outp[(y*64+x)*FD];
                if(permout){
                    d[(oc & ~7) + iperm[2*c]]   = totf(v0);
                    d[(oc & ~7) + iperm[2*c+1]] = totf(v1);
                } else {
                    *(float2*)&d[oc] = make_float2(v0, v1);
                }
            }
        }
    }
}

// ---------------- bilinear grid sample over 3 planes, accumulate ----------------
__global__ void k_sample(const float* __restrict__ query, float* __restrict__ out){
    int gid = blockIdx.x*256 + threadIdx.x;
    int w = gid >> 5, lane = gid & 31;
    if(w >= BN) return;
    int b = w / NP;
    float q0 = query[w*3+0], q1 = query[w*3+1], q2 = query[w*3+2];
    float a0[4] = {0,0,0,0}, a1[4] = {0,0,0,0};
    #pragma unroll
    for(int pl=0; pl<3; pl++){
        float qa = (pl==2) ? q1 : q0;
        float qb = (pl==1) ? q1 : q2;
        float gx = qa*2.0f - 1.0f, gy = qb*2.0f - 1.0f;
        float x = ((gx + 1.0f)*64.0f - 1.0f)*0.5f;
        float y = ((gy + 1.0f)*64.0f - 1.0f)*0.5f;
        x = fminf(fmaxf(x, 0.0f), 63.0f);
        y = fminf(fmaxf(y, 0.0f), 63.0f);
        float x0f = floorf(x), y0f = floorf(y);
        int x0 = (int)x0f, y0 = (int)y0f;
        int x1 = min(x0+1, 63), y1 = min(y0+1, 63);
        float wx = x - x0f, wy = y - y0f;
        const float* f = &g_fec[(pl*BATCH + b)*R2*FD];
        float ww[4] = {(1.f-wx)*(1.f-wy), wx*(1.f-wy), (1.f-wx)*wy, wx*wy};
        int pix[4] = {y0*64+x0, y0*64+x1, y1*64+x0, y1*64+x1};
        #pragma unroll
        for(int tp=0; tp<4; tp++){
            const float* base = f + pix[tp]*FD;
            float4 v0 = *(const float4*)&base[lane*4];
            float4 v1 = *(const float4*)&base[128 + lane*4];
            float g = ww[tp];
            a0[0]+=g*v0.x; a0[1]+=g*v0.y; a0[2]+=g*v0.z; a0[3]+=g*v0.w;
            a1[0]+=g*v1.x; a1[1]+=g*v1.y; a1[2]+=g*v1.z; a1[3]+=g*v1.w;
        }
    }
    float* ob = &out[w*FD];
    *(float4*)&ob[lane*4]       = make_float4(a0[0],a0[1],a0[2],a0[3]);
    *(float4*)&ob[128+lane*4]   = make_float4(a1[0],a1[1],a1[2],a1[3]);
}

// ---------------- launch ----------------
extern "C" void kernel_launch(void* const* d_in, const int* in_sizes, int n_in,
                              void* d_out, int out_size)
{
    const float* p    = (const float*)d_in[0];
    const float* qry  = (const float*)d_in[1];
    const float* fcW  = (const float*)d_in[2];
    const float* fcb  = (const float*)d_in[3];
    const float* W0   = (const float*)d_in[4];
    const float* b0   = (const float*)d_in[5];
    const float* W1   = (const float*)d_in[6];
    const float* b1   = (const float*)d_in[7];
    const float* Ws   = (const float*)d_in[8];
    const float* Wc   = (const float*)d_in[9];
    const float* bc   = (const float*)d_in[10];
    const float* C1W  = (const float*)d_in[11];
    const float* C1b  = (const float*)d_in[12];
    const float* C2W  = (const float*)d_in[13];
    const float* C2b  = (const float*)d_in[14];
    float* out = (float*)d_out;

    cudaFuncSetAttribute(k_block,    cudaFuncAttributeMaxDynamicSharedMemorySize, SM_BLOCK);
    cudaFuncSetAttribute(k_fcc_bins, cudaFuncAttributeMaxDynamicSharedMemorySize, SM_FCC);
    cudaFuncSetAttribute(k_conv,     cudaFuncAttributeMaxDynamicSharedMemorySize, SM_CONV);

    void *binsum2_p, *bincnt2_p, *nsum_p, *cnt3_p, *fea_p, *feb_p, *fec_p, *wt_p;
    cudaGetSymbolAddress(&binsum2_p, g_binsum2);
    cudaGetSymbolAddress(&bincnt2_p, g_bincnt2);
    cudaGetSymbolAddress(&nsum_p,    g_nsum);
    cudaGetSymbolAddress(&cnt3_p,    g_cnt3);
    cudaGetSymbolAddress(&fea_p,     g_fea);
    cudaGetSymbolAddress(&feb_p,     g_feb);
    cudaGetSymbolAddress(&fec_p,     g_fec);
    cudaGetSymbolAddress(&wt_p,      g_wt);

    k_idx<<<(BN+255)/256, 256>>>(p);
    k_wblk<<<(3*20480+255)/256, 256>>>(W0, W1, Ws);

    cudaMemsetAsync(binsum2_p, 0, (size_t)2*BATCH*R2*HID*4);
    cudaMemsetAsync(bincnt2_p, 0, (size_t)2*BATCH*R2*4);
    cudaMemsetAsync(nsum_p,    0, (size_t)NBROW*HID*4);
    cudaMemsetAsync(cnt3_p,    0, (size_t)NBROW*4);

    k_block<<<BATCH*NT, 256, SM_BLOCK>>>(0, p, fcW, fcb, b0, b1);
    k_block<<<BATCH*NT, 256, SM_BLOCK>>>(1, p, fcW, fcb, b0 + HID, b1 + HID);
    k_block<<<BATCH*NT, 256, SM_BLOCK>>>(2, p, fcW, fcb, b0 + 2*HID, b1 + 2*HID);

    k_wfcc<<<16384/256, 256>>>(Wc);
    k_fcc_bins<<<NBROW/64, 256, SM_FCC>>>(bc);

    k_wtrans<<<(2*2304*FD)/256, 256>>>(C1W, C2W);
    k_conv<<<12*32*4, 256, SM_CONV>>>((const float*)fea_p, (float*)feb_p,
                                      (const float*)wt_p,               C1b, 1);
    k_conv<<<12*32*4, 256, SM_CONV>>>((const float*)feb_p, (float*)fec_p,
                                      (const float*)wt_p + 2304*FD,     C2b, 0);

    k_sample<<<(BN*32)/256, 256>>>(qry, out);
}

// round 11
// speedup vs baseline: 1.0794x; 1.0794x over previous
#include <cuda_runtime.h>

#define BATCH 4
#define NP 30000
#define BN (BATCH*NP)
#define HID 64
#define FD 256
#define R2 4096
#define NT 469   /* ceil(NP/64) */
#define NBROW (3*BATCH*R2)

// ---------------- scratch (no allocation allowed) ----------------
__device__ float g_net[BN*HID];
__device__ int   g_idx[3*BN];
__device__ float g_binsum2[2*BATCH*R2*HID];
__device__ float g_bincnt2[2*BATCH*R2];
__device__ float g_nsum[NBROW*HID];
__device__ float g_cnt3[NBROW];
__device__ __align__(128) float g_fea[NBROW*FD];     // conv1 in  (permuted tf32)
__device__ __align__(128) float g_feb[NBROW*FD];     // conv1 out (permuted tf32)
__device__ __align__(128) float g_fec[NBROW*FD];     // conv2 out (natural fp32)
__device__ __align__(128) float g_wt[2*2304*FD];     // conv tf32 wt [conv][ch][kk][oc][icp]  (R9 layout)
__device__ __align__(128) float g_wblk[3*20480];     // resblock tf32 wt (pair-interleaved fragments)
__device__ __align__(128) float g_wfcc[16384];       // fc_c tf32 wt [8kc][256n][8s]

// ---------------- helpers ----------------
__device__ __forceinline__ float totf(float x){
    unsigned u; asm("cvt.rna.tf32.f32 %0, %1;" : "=r"(u) : "f"(x));
    return __uint_as_float(u);
}
__device__ __forceinline__ void cpa(unsigned d, const void* s, int sz){
    asm volatile("cp.async.cg.shared.global [%0], [%1], 16, %2;" :: "r"(d), "l"(s), "r"(sz));
}
#define CP_COMMIT asm volatile("cp.async.commit_group;")
#define CP_WAIT0  asm volatile("cp.async.wait_group 0;")

__device__ __forceinline__ void mma8(float* d, uint2 ar0, uint2 ar1, uint2 b){
    asm volatile("mma.sync.aligned.m16n8k8.row.col.f32.tf32.tf32.f32 "
        "{%0,%1,%2,%3}, {%4,%5,%6,%7}, {%8,%9}, {%0,%1,%2,%3};"
        : "+f"(d[0]),"+f"(d[1]),"+f"(d[2]),"+f"(d[3])
        : "r"(ar0.x),"r"(ar1.x),"r"(ar0.y),"r"(ar1.y), "r"(b.x),"r"(b.y));
}
__device__ __forceinline__ void mma8v(float* d, uint4 a, unsigned b0, unsigned b1){
    asm volatile("mma.sync.aligned.m16n8k8.row.col.f32.tf32.tf32.f32 "
        "{%0,%1,%2,%3}, {%4,%5,%6,%7}, {%8,%9}, {%0,%1,%2,%3};"
        : "+f"(d[0]),"+f"(d[1]),"+f"(d[2]),"+f"(d[3])
        : "r"(a.x),"r"(a.y),"r"(a.z),"r"(a.w), "r"(b0),"r"(b1));
}

// ---------------- bin indices ----------------
__device__ __forceinline__ int binof(float v){
    const float DEN = (float)(1.0 + 0.1 + 1e-6);
    float w = (v + 0.5f) / DEN;
    w = fminf(fmaxf(w, 0.0f), (float)(1.0 - 1e-6));
    return (int)(w * 64.0f);
}

__global__ void k_idx(const float* __restrict__ p){
    int i = blockIdx.x*256 + threadIdx.x;
    if(i >= BN) return;
    float x = p[i*3+0], y = p[i*3+1], z = p[i*3+2];
    int bx = binof(x), by = binof(y), bz = binof(z);
    g_idx[0*BN+i] = bx + 64*bz;
    g_idx[1*BN+i] = bx + 64*by;
    g_idx[2*BN+i] = by + 64*bz;
}

// ---------------- resblock weight prep: pair-interleaved fragments ----------------
// per mode: [0,8192) W0 [16kc][512]; [8192,12288) W1 [8kc][512]; [12288,20480) Ws [16kc][512]
// within 512: e = wn*256 + ntp*128 + qn*16 + s*2 + g ; n = wn*32+ntp*16+g*8+qn ; k = kc*8+(s&1)*4+(s>>1)
__global__ void k_wblk(const float* __restrict__ W0, const float* __restrict__ W1,
                       const float* __restrict__ Ws){
    int i = blockIdx.x*256 + threadIdx.x;
    if(i >= 3*20480) return;
    int m = i / 20480, r = i - m*20480;
    const float* src; int kc, e, K;
    if(r < 8192){ src = W0 + m*64*128; kc = r>>9; e = r&511; K = 128; }
    else if(r < 12288){ int q = r-8192; src = W1 + m*64*64; kc = q>>9; e = q&511; K = 64; }
    else { int q = r-12288; src = Ws + m*64*128; kc = q>>9; e = q&511; K = 128; }
    int wn = e>>8, ntp = (e>>7)&1, qn = (e>>4)&7, s = (e>>1)&7, g = e&1;
    int n = wn*32 + ntp*16 + g*8 + qn;
    int k = kc*8 + (s&1)*4 + (s>>1);
    g_wblk[i] = totf(src[n*K + k]);
}

// ---------------- fc_c weight prep ----------------
__global__ void k_wfcc(const float* __restrict__ Wc){
    int i = blockIdx.x*256 + threadIdx.x;
    if(i >= 16384) return;
    int s = i & 7, n = (i>>3)&255, kc = i>>11;
    int k = kc*8 + (s&1)*4 + (s>>1);
    g_wfcc[i] = totf(Wc[n*64 + k]);
}

// ---------------- fused resblock + scatter epilogue: TF32 mma, B-frags via LDG, 3 CTA/SM ----------------
// smem = x_s only (8192 floats = 32KB); h aliases first 8 kc after pass 1
#define SM_BLOCK (8192*4)

__global__ void __launch_bounds__(256, 3) k_block(int mode, const float* __restrict__ p,
                        const float* __restrict__ fcW, const float* __restrict__ fcb,
                        const float* __restrict__ b0g, const float* __restrict__ b1g)
{
    extern __shared__ float sm[];
    float* x_s = sm;               // [16kc][512] interleaved frags

    int t = threadIdx.x;
    int lane = t & 31, w = t >> 5;
    int wm = w & 3, wn = w >> 2;
    int q = lane >> 2, c = lane & 3;
    int s0 = (c < 2) ? 4*c     : 4*c - 7;   // slot of k=2c
    int s1 = (c < 2) ? 4*c + 2 : 4*c - 5;   // slot of k=2c+1

    int b = blockIdx.x / NT, tile = blockIdx.x % NT;
    int pt0 = tile*64;
    int npts = min(64, NP - pt0);
    int gbase = b*NP + pt0;

    const float* __restrict__ wg0 = g_wblk + mode*20480;   // w0 [16kc][512]
    const float* __restrict__ wg1 = wg0 + 8192;            // w1 [8kc][512]
    const float* __restrict__ wgs = wg0 + 12288;           // ws [16kc][512]

    // stage x tile (interleaved frag layout): (pt, slot) -> kc*512 + (pt>>4)*128 + (pt&7)*16 + slot*2 + ((pt>>3)&1)
    if(mode == 0){
        for(int e=t; e<2048; e+=256){
            int pt = e>>5, gg = e&31;
            int kc = gg>>1, half = gg&1;
            int kb = kc*8 + half*4;
            float* d = &x_s[kc*512 + (pt>>4)*128 + (pt&7)*16 + ((pt>>3)&1) + half*2];
            if(pt < npts){
                int gp = (gbase + pt)*3;
                float px = p[gp], py = p[gp+1], pz = p[gp+2];
                #pragma unroll
                for(int i2=0;i2<4;i2++){
                    int j = kb + i2;
                    float v = fcb[j] + px*fcW[j*3] + py*fcW[j*3+1] + pz*fcW[j*3+2];
                    d[4*i2] = totf(v);
                }
            } else {
                d[0]=0.f; d[4]=0.f; d[8]=0.f; d[12]=0.f;
            }
        }
    } else {
        const float* bs   = g_binsum2 + ((mode-1)&1)*(BATCH*R2*HID);
        const float* bcnt = g_bincnt2 + ((mode-1)&1)*(BATCH*R2);
        for(int e=t; e<2048; e+=256){
            int pt = e>>5, gg = e&31;
            int kc = gg>>1, half = gg&1;
            float4 v = make_float4(0.f,0.f,0.f,0.f);
            if(pt < npts){
                int gi = gbase + pt;
                if(kc < 8) v = *(const float4*)&g_net[gi*HID + kc*8 + half*4];
                else {
                    int row = b*R2 + g_idx[gi];
                    float inv = 1.0f / fmaxf(bcnt[row], 1.0f);
                    v = *(const float4*)&bs[row*HID + (kc-8)*8 + half*4];
                    v.x*=inv; v.y*=inv; v.z*=inv; v.w*=inv;
                }
            }
            float* d = &x_s[kc*512 + (pt>>4)*128 + (pt&7)*16 + ((pt>>3)&1) + half*2];
            d[0]=totf(v.x); d[4]=totf(v.y); d[8]=totf(v.z); d[12]=totf(v.w);
        }
    }
    __syncthreads();

    int rb = wm*16;
    int r0 = rb + q, r1 = rb + q + 8;
    int abase = wm*128 + q*16 + 4*c;
    int bbase = wn*256 + q*16 + 4*c;

    // PASS 1 (fused): aH = x@W0^T ; aS = x@Ws^T  (B fragments straight from global: L1/L2-hot)
    float aH[4][4], aS[4][4];
    #pragma unroll
    for(int nt=0;nt<4;nt++){
        aH[nt][0]=aH[nt][1]=aH[nt][2]=aH[nt][3]=0.f;
        aS[nt][0]=aS[nt][1]=aS[nt][2]=aS[nt][3]=0.f;
    }
    #pragma unroll 4
    for(int kc=0; kc<16; kc++){
        uint4 av = *(const uint4*)&x_s[kc*512 + abase];
        #pragma unroll
        for(int ntp=0; ntp<2; ntp++){
            uint4 w0v = *(const uint4*)&wg0[kc*512 + bbase + ntp*128];
            uint4 wsv = *(const uint4*)&wgs[kc*512 + bbase + ntp*128];
            mma8v(aH[2*ntp],   av, w0v.x, w0v.z);
            mma8v(aH[2*ntp+1], av, w0v.y, w0v.w);
            mma8v(aS[2*ntp],   av, wsv.x, wsv.z);
            mma8v(aS[2*ntp+1], av, wsv.y, wsv.w);
        }
    }
    __syncthreads();   // pass-1 x_s reads complete

    // write h into x_s alias (first 8 kc region), interleaved layout
    #pragma unroll
    for(int nt=0; nt<4; nt++){
        int j0 = wn*32 + nt*8 + 2*c;
        float2 bb = *(const float2*)&b0g[j0];
        float* dl = &x_s[(j0>>3)*512 + wm*128 + q*16];
        dl[s0*2 + 0] = totf(fmaxf(aH[nt][0]+bb.x, 0.f));   // (r0, k=2c)
        dl[s1*2 + 0] = totf(fmaxf(aH[nt][1]+bb.y, 0.f));   // (r0, k=2c+1)
        dl[s0*2 + 1] = totf(fmaxf(aH[nt][2]+bb.x, 0.f));   // (r1, k=2c)
        dl[s1*2 + 1] = totf(fmaxf(aH[nt][3]+bb.y, 0.f));   // (r1, k=2c+1)
    }
    __syncthreads();

    // PASS 2: aD = h @ W1^T
    float aD[4][4];
    #pragma unroll
    for(int nt=0;nt<4;nt++){ aD[nt][0]=aD[nt][1]=aD[nt][2]=aD[nt][3]=0.f; }
    #pragma unroll
    for(int kc=0; kc<8; kc++){
        uint4 av = *(const uint4*)&x_s[kc*512 + abase];
        #pragma unroll
        for(int ntp=0; ntp<2; ntp++){
            uint4 wv = *(const uint4*)&wg1[kc*512 + bbase + ntp*128];
            mma8v(aD[2*ntp],   av, wv.x, wv.z);
            mma8v(aD[2*ntp+1], av, wv.y, wv.w);
        }
    }
    #pragma unroll
    for(int nt=0; nt<4; nt++){
        int j0 = wn*32 + nt*8 + 2*c;
        float2 bb = *(const float2*)&b1g[j0];
        aD[nt][0] = fmaxf(aD[nt][0]+bb.x, 0.f) + aS[nt][0];
        aD[nt][1] = fmaxf(aD[nt][1]+bb.y, 0.f) + aS[nt][1];
        aD[nt][2] = fmaxf(aD[nt][2]+bb.x, 0.f) + aS[nt][2];
        aD[nt][3] = fmaxf(aD[nt][3]+bb.y, 0.f) + aS[nt][3];
    }

    // ---------------- epilogue ----------------
    if(mode < 2){
        float* bs   = g_binsum2 + (mode&1)*(BATCH*R2*HID);
        float* bcnt = g_bincnt2 + (mode&1)*(BATCH*R2);
        if(wn==0 && c==0){
            if(r0 < npts) atomicAdd(&bcnt[b*R2 + g_idx[gbase+r0]], 1.0f);
            if(r1 < npts) atomicAdd(&bcnt[b*R2 + g_idx[gbase+r1]], 1.0f);
        }
        int bin0 = (r0 < npts) ? (b*R2 + g_idx[gbase+r0]) : -1;
        int bin1 = (r1 < npts) ? (b*R2 + g_idx[gbase+r1]) : -1;
        #pragma unroll
        for(int nt=0; nt<4; nt++){
            int j0 = wn*32 + nt*8 + 2*c;
            if(bin0 >= 0){
                *(float2*)&g_net[(gbase+r0)*HID + j0] = make_float2(aD[nt][0], aD[nt][1]);
                atomicAdd(&bs[bin0*HID + j0],   aD[nt][0]);
                atomicAdd(&bs[bin0*HID + j0+1], aD[nt][1]);
            }
            if(bin1 >= 0){
                *(float2*)&g_net[(gbase+r1)*HID + j0] = make_float2(aD[nt][2], aD[nt][3]);
                atomicAdd(&bs[bin1*HID + j0],   aD[nt][2]);
                atomicAdd(&bs[bin1*HID + j0+1], aD[nt][3]);
            }
        }
    } else {
        if(wn==0 && c==0){
            #pragma unroll
            for(int hh=0;hh<2;hh++){
                int r = rb + q + hh*8;
                if(r < npts){
                    int gi = gbase + r;
                    #pragma unroll
                    for(int pl=0;pl<3;pl++)
                        atomicAdd(&g_cnt3[(pl*BATCH+b)*R2 + g_idx[pl*BN+gi]], 1.0f);
                }
            }
        }
        int rowp[2][3];
        #pragma unroll
        for(int hh=0;hh<2;hh++){
            int r = rb + q + hh*8;
            if(r < npts){
                int gi = gbase + r;
                #pragma unroll
                for(int pl=0;pl<3;pl++)
                    rowp[hh][pl] = (pl*BATCH+b)*R2 + g_idx[pl*BN+gi];
            } else {
                rowp[hh][0]=rowp[hh][1]=rowp[hh][2]=-1;
            }
        }
        #pragma unroll
        for(int nt=0; nt<4; nt++){
            int j0 = wn*32 + nt*8 + 2*c;
            #pragma unroll
            for(int hh=0;hh<2;hh++){
                if(rowp[hh][0] >= 0){
                    float v0 = aD[nt][hh*2+0], v1 = aD[nt][hh*2+1];
                    #pragma unroll
                    for(int pl=0;pl<3;pl++){
                        atomicAdd(&g_nsum[rowp[hh][pl]*HID + j0],   v0);
                        atomicAdd(&g_nsum[rowp[hh][pl]*HID + j0+1], v1);
                    }
                }
            }
        }
    }
}

// ---------------- bin GEMM fc_c (TF32 mma) ----------------
#define SM_FCC ((4096 + 16384)*4)
__global__ void __launch_bounds__(256) k_fcc_bins(const float* __restrict__ bc){
    extern __shared__ float sm[];
    float* x_s = sm;             // [8kc][64pt][8]
    float* w_s = sm + 4096;      // [8kc][256n][8]
    unsigned ws_u = (unsigned)__cvta_generic_to_shared(w_s);
    int t = threadIdx.x;
    int lane = t & 31, w = t >> 5;
    int wm = w & 1, wn = w >> 1;
    int q = lane >> 2, c = lane & 3;
    int r0b = blockIdx.x*64;

    for(int e=t; e<4096; e+=256)
        cpa(ws_u + (unsigned)e*16, g_wfcc + e*4, 16);
    CP_COMMIT;

    for(int e=t; e<1024; e+=256){
        int pt = e>>4, g = e&15;
        int kc = g>>1, half = g&1;
        int row = r0b + pt;
        float inv = 1.0f / fmaxf(g_cnt3[row], 1.0f);
        float4 v = *(const float4*)&g_nsum[row*HID + kc*8 + half*4];
        float* d = &x_s[kc*512 + pt*8 + half];
        d[0]=totf(v.x*inv); d[2]=totf(v.y*inv); d[4]=totf(v.z*inv); d[6]=totf(v.w*inv);
    }
    CP_WAIT0;
    __syncthreads();

    int rb = wm*32;
    float acc[2][8][4];
    #pragma unroll
    for(int mt=0;mt<2;mt++)
        #pragma unroll
        for(int nt=0;nt<8;nt++){ acc[mt][nt][0]=acc[mt][nt][1]=acc[mt][nt][2]=acc[mt][nt][3]=0.f; }
    #pragma unroll
    for(int kc=0; kc<8; kc++){
        uint2 a[2][2];
        #pragma unroll
        for(int mt=0;mt<2;mt++){
            a[mt][0] = *(const uint2*)&x_s[kc*512 + (rb+mt*16+q)*8 + 2*c];
            a[mt][1] = *(const uint2*)&x_s[kc*512 + (rb+mt*16+q+8)*8 + 2*c];
        }
        const float* wb = &w_s[kc*2048 + (wn*64 + q)*8 + 2*c];
        #pragma unroll
        for(int nt=0; nt<8; nt++){
            uint2 bb = *(const uint2*)&wb[nt*64];
            mma8(acc[0][nt], a[0][0], a[0][1], bb);
            mma8(acc[1][nt], a[1][0], a[1][1], bb);
        }
    }

    const int iperm[8] = {0,2,4,6,1,3,5,7};
    #pragma unroll
    for(int nt=0; nt<8; nt++){
        int j0 = wn*64 + nt*8 + 2*c;
        float2 bb = *(const float2*)&bc[j0];
        #pragma unroll
        for(int mt=0;mt<2;mt++){
            #pragma unroll
            for(int half=0; half<2; half++){
                int r = rb + mt*16 + q + half*8;
                int row = r0b + r;
                float gate = (g_cnt3[row] > 0.f) ? 1.f : 0.f;
                float* d = &g_fea[row*FD + (j0 & ~7)];
                d[iperm[2*c]]   = totf(gate*(acc[mt][nt][half*2+0]+bb.x));
                d[iperm[2*c+1]] = totf(gate*(acc[mt][nt][half*2+1]+bb.y));
            }
        }
    }
}

// ---------------- conv weight prep (R9 layout): [conv][ch][kk][oc][icp] ----------------
__global__ void k_wtrans(const float* __restrict__ Wa, const float* __restrict__ Wb){
    int i = blockIdx.x*256 + threadIdx.x;
    if(i >= 2*2304*FD) return;
    int cI = i / (2304*FD);
    int rem = i - cI*(2304*FD);
    int j  = rem & 7;
    int r2 = rem >> 3;
    int oc = r2 & 255;
    int r3 = r2 >> 8;
    int kk = r3 % 9, ch = r3 / 9;
    const int perm[8] = {0,4,1,5,2,6,3,7};
    int ic = ch*8 + perm[j];
    const float* W = cI ? Wb : Wa;
    g_wt[i] = totf(W[oc*2304 + ic*9 + kk]);
}

// ---------------- 3x3 conv 256->256, TF32 mma, cp.async, 128 oc/block, 2 CTA/SM (R9) ----------------
#define SM_CONV ((2*2112 + 2*9216)*4)

__global__ void __launch_bounds__(256, 2) k_conv(
        const float* __restrict__ in, float* __restrict__ out,
        const float* __restrict__ wt, const float* __restrict__ bias, int permout)
{
    extern __shared__ float sm[];
    float* ibuf = sm;
    float* wbuf = sm + 2*2112;
    unsigned ib_u = (unsigned)__cvta_generic_to_shared(ibuf);
    unsigned wb_u = (unsigned)__cvta_generic_to_shared(wbuf);
    int t = threadIdx.x;
    int lane = t & 31, w = t >> 5;
    int wm = w & 3, wn = w >> 2;
    int q = lane >> 2, c = lane & 3;

    int ocb = blockIdx.x & 1;
    int r = blockIdx.x >> 1;
    int rp = r & 31;
    int pb = r >> 5;
    const float* inp  = in  + pb*R2*FD;
    float*       outp = out + pb*R2*FD;
    int y0 = rp*2;
    int px_base = wm*32;

    float acc[2][8][4];
    #pragma unroll
    for(int mt=0; mt<2; mt++)
        #pragma unroll
        for(int nt=0; nt<8; nt++){
            acc[mt][nt][0]=0.f; acc[mt][nt][1]=0.f; acc[mt][nt][2]=0.f; acc[mt][nt][3]=0.f;
        }

    auto stage = [&](int ch, int buf){
        for(int e=t; e<528; e+=256){
            int pos = e>>1, half = e&1;
            int rr = pos/66, cc = pos - rr*66;
            int yy = y0 + rr - 1, xx = cc - 1;
            bool ok = (yy >= 0 && yy < 64 && (unsigned)xx < 64u);
            const float* src = inp + ((ok ? (yy*64+xx) : 0)*FD + ch*8 + half*4);
            cpa(ib_u + (unsigned)(buf*2112*4 + pos*32 + half*16), src, ok ? 16 : 0);
        }
        const float* wsrc = wt + (size_t)ch*18432 + ocb*1024;
        for(int e=t; e<2304; e+=256){
            int kk = e>>8, rem = e&255;
            cpa(wb_u + (unsigned)(buf*9216*4 + kk*4096 + rem*16),
                wsrc + kk*2048 + rem*4, 16);
        }
        CP_COMMIT;
    };

    stage(0, 0);
    for(int ch=0; ch<32; ch++){
        int cur = ch & 1;
        CP_WAIT0;
        __syncthreads();
        if(ch < 31) stage(ch+1, 1-cur);
        const float* in_s = ibuf + cur*2112;
        const float* w_s  = wbuf + cur*9216;
        #pragma unroll
        for(int kk=0; kk<9; kk++){
            int ky = kk/3, kx = kk - ky*3;
            uint2 a[2][2];
            #pragma unroll
            for(int mt=0; mt<2; mt++){
                int px0 = px_base + mt*16 + q;
                a[mt][0] = *(const uint2*)&in_s[(((px0>>6)+ky)*66 + (px0&63)+kx)*8 + 2*c];
                int px1 = px0 + 8;
                a[mt][1] = *(const uint2*)&in_s[(((px1>>6)+ky)*66 + (px1&63)+kx)*8 + 2*c];
            }
            const float* wb = &w_s[kk*1024 + (wn*64 + q)*8 + 2*c];
            #pragma unroll
            for(int nt=0; nt<8; nt++){
                uint2 b = *(const uint2*)&wb[nt*64];
                mma8(acc[0][nt], a[0][0], a[0][1], b);
                mma8(acc[1][nt], a[1][0], a[1][1], b);
            }
        }
        __syncthreads();
    }

    int o_base = ocb*128 + wn*64;
    const int iperm[8] = {0,2,4,6,1,3,5,7};
    #pragma unroll
    for(int nt=0; nt<8; nt++){
        int oc = o_base + nt*8 + 2*c;
        float2 bb = *(const float2*)&bias[oc];
        #pragma unroll
        for(int mt=0; mt<2; mt++){
            #pragma unroll
            for(int half=0; half<2; half++){
                int px = px_base + mt*16 + q + half*8;
                int y = y0 + (px>>6), x = px&63;
                float v0 = fmaxf(acc[mt][nt][half*2+0]+bb.x, 0.f);
                float v1 = fmaxf(acc[mt][nt][half*2+1]+bb.y, 0.f);
                float* d = &outp[(y*64+x)*FD];
                if(permout){
                    d[(oc & ~7) + iperm[2*c]]   = totf(v0);
                    d[(oc & ~7) + iperm[2*c+1]] = totf(v1);
                } else {
                    *(float2*)&d[oc] = make_float2(v0, v1);
                }
            }
        }
    }
}

// ---------------- bilinear grid sample over 3 planes, accumulate ----------------
__global__ void k_sample(const float* __restrict__ query, float* __restrict__ out){
    int gid = blockIdx.x*256 + threadIdx.x;
    int w = gid >> 5, lane = gid & 31;
    if(w >= BN) return;
    int b = w / NP;
    float q0 = query[w*3+0], q1 = query[w*3+1], q2 = query[w*3+2];
    float a0[4] = {0,0,0,0}, a1[4] = {0,0,0,0};
    #pragma unroll
    for(int pl=0; pl<3; pl++){
        float qa = (pl==2) ? q1 : q0;
        float qb = (pl==1) ? q1 : q2;
        float gx = qa*2.0f - 1.0f, gy = qb*2.0f - 1.0f;
        float x = ((gx + 1.0f)*64.0f - 1.0f)*0.5f;
        float y = ((gy + 1.0f)*64.0f - 1.0f)*0.5f;
        x = fminf(fmaxf(x, 0.0f), 63.0f);
        y = fminf(fmaxf(y, 0.0f), 63.0f);
        float x0f = floorf(x), y0f = floorf(y);
        int x0 = (int)x0f, y0 = (int)y0f;
        int x1 = min(x0+1, 63), y1 = min(y0+1, 63);
        float wx = x - x0f, wy = y - y0f;
        const float* f = &g_fec[(pl*BATCH + b)*R2*FD];
        float ww[4] = {(1.f-wx)*(1.f-wy), wx*(1.f-wy), (1.f-wx)*wy, wx*wy};
        int pix[4] = {y0*64+x0, y0*64+x1, y1*64+x0, y1*64+x1};
        #pragma unroll
        for(int tp=0; tp<4; tp++){
            const float* base = f + pix[tp]*FD;
            float4 v0 = *(const float4*)&base[lane*4];
            float4 v1 = *(const float4*)&base[128 + lane*4];
            float g = ww[tp];
            a0[0]+=g*v0.x; a0[1]+=g*v0.y; a0[2]+=g*v0.z; a0[3]+=g*v0.w;
            a1[0]+=g*v1.x; a1[1]+=g*v1.y; a1[2]+=g*v1.z; a1[3]+=g*v1.w;
        }
    }
    float* ob = &out[w*FD];
    *(float4*)&ob[lane*4]       = make_float4(a0[0],a0[1],a0[2],a0[3]);
    *(float4*)&ob[128+lane*4]   = make_float4(a1[0],a1[1],a1[2],a1[3]);
}

// ---------------- launch ----------------
extern "C" void kernel_launch(void* const* d_in, const int* in_sizes, int n_in,
                              void* d_out, int out_size)
{
    const float* p    = (const float*)d_in[0];
    const float* qry  = (const float*)d_in[1];
    const float* fcW  = (const float*)d_in[2];
    const float* fcb  = (const float*)d_in[3];
    const float* W0   = (const float*)d_in[4];
    const float* b0   = (const float*)d_in[5];
    const float* W1   = (const float*)d_in[6];
    const float* b1   = (const float*)d_in[7];
    const float* Ws   = (const float*)d_in[8];
    const float* Wc   = (const float*)d_in[9];
    const float* bc   = (const float*)d_in[10];
    const float* C1W  = (const float*)d_in[11];
    const float* C1b  = (const float*)d_in[12];
    const float* C2W  = (const float*)d_in[13];
    const float* C2b  = (const float*)d_in[14];
    float* out = (float*)d_out;

    cudaFuncSetAttribute(k_block,    cudaFuncAttributeMaxDynamicSharedMemorySize, SM_BLOCK);
    cudaFuncSetAttribute(k_fcc_bins, cudaFuncAttributeMaxDynamicSharedMemorySize, SM_FCC);
    cudaFuncSetAttribute(k_conv,     cudaFuncAttributeMaxDynamicSharedMemorySize, SM_CONV);

    void *binsum2_p, *bincnt2_p, *nsum_p, *cnt3_p, *fea_p, *feb_p, *fec_p, *wt_p;
    cudaGetSymbolAddress(&binsum2_p, g_binsum2);
    cudaGetSymbolAddress(&bincnt2_p, g_bincnt2);
    cudaGetSymbolAddress(&nsum_p,    g_nsum);
    cudaGetSymbolAddress(&cnt3_p,    g_cnt3);
    cudaGetSymbolAddress(&fea_p,     g_fea);
    cudaGetSymbolAddress(&feb_p,     g_feb);
    cudaGetSymbolAddress(&fec_p,     g_fec);
    cudaGetSymbolAddress(&wt_p,      g_wt);

    k_idx<<<(BN+255)/256, 256>>>(p);
    k_wblk<<<(3*20480+255)/256, 256>>>(W0, W1, Ws);

    cudaMemsetAsync(binsum2_p, 0, (size_t)2*BATCH*R2*HID*4);
    cudaMemsetAsync(bincnt2_p, 0, (size_t)2*BATCH*R2*4);
    cudaMemsetAsync(nsum_p,    0, (size_t)NBROW*HID*4);
    cudaMemsetAsync(cnt3_p,    0, (size_t)NBROW*4);

    k_block<<<BATCH*NT, 256, SM_BLOCK>>>(0, p, fcW, fcb, b0, b1);
    k_block<<<BATCH*NT, 256, SM_BLOCK>>>(1, p, fcW, fcb, b0 + HID, b1 + HID);
    k_block<<<BATCH*NT, 256, SM_BLOCK>>>(2, p, fcW, fcb, b0 + 2*HID, b1 + 2*HID);

    k_wfcc<<<16384/256, 256>>>(Wc);
    k_fcc_bins<<<NBROW/64, 256, SM_FCC>>>(bc);

    k_wtrans<<<(2*2304*FD)/256, 256>>>(C1W, C2W);
    k_conv<<<12*32*2, 256, SM_CONV>>>((const float*)fea_p, (float*)feb_p,
                                      (const float*)wt_p,               C1b, 1);
    k_conv<<<12*32*2, 256, SM_CONV>>>((const float*)feb_p, (float*)fec_p,
                                      (const float*)wt_p + 2304*FD,     C2b, 0);

    k_sample<<<(BN*32)/256, 256>>>(qry, out);
}

// round 12
// speedup vs baseline: 1.5345x; 1.4217x over previous
#include <cuda_runtime.h>
#include <cuda_fp16.h>

#define BATCH 4
#define NP 30000
#define BN (BATCH*NP)
#define HID 64
#define FD 256
#define R2 4096
#define NT 469   /* ceil(NP/64) */
#define NBROW (3*BATCH*R2)

// ---------------- scratch (no allocation allowed) ----------------
__device__ float g_net[BN*HID];
__device__ int   g_idx[3*BN];
__device__ float g_binsum2[2*BATCH*R2*HID];
__device__ float g_bincnt2[2*BATCH*R2];
__device__ float g_nsum[NBROW*HID];
__device__ float g_cnt3[NBROW];
__device__ __align__(128) __half g_fea[NBROW*FD];    // conv1 in  (fp16 interleaved)
__device__ __align__(128) __half g_feb[NBROW*FD];    // conv1 out (fp16 interleaved)
__device__ __align__(128) float  g_fec[NBROW*FD];    // conv2 out (natural fp32)
__device__ __align__(128) __half g_wt[2*589824];     // conv fp16 wt [conv][ch16][kk][oc][16 interleaved]
__device__ __align__(128) float g_wblk[3*20480];     // resblock tf32 wt (pair-interleaved fragments)
__device__ __align__(128) float g_wfcc[16384];       // fc_c tf32 wt [8kc][256n][8s]

// ---------------- helpers ----------------
__device__ __forceinline__ float totf(float x){
    unsigned u; asm("cvt.rna.tf32.f32 %0, %1;" : "=r"(u) : "f"(x));
    return __uint_as_float(u);
}
__device__ __forceinline__ void cpa(unsigned d, const void* s, int sz){
    asm volatile("cp.async.cg.shared.global [%0], [%1], 16, %2;" :: "r"(d), "l"(s), "r"(sz));
}
#define CP_COMMIT asm volatile("cp.async.commit_group;")
#define CP_WAIT0  asm volatile("cp.async.wait_group 0;")

__device__ __forceinline__ void mma8(float* d, uint2 ar0, uint2 ar1, uint2 b){
    asm volatile("mma.sync.aligned.m16n8k8.row.col.f32.tf32.tf32.f32 "
        "{%0,%1,%2,%3}, {%4,%5,%6,%7}, {%8,%9}, {%0,%1,%2,%3};"
        : "+f"(d[0]),"+f"(d[1]),"+f"(d[2]),"+f"(d[3])
        : "r"(ar0.x),"r"(ar1.x),"r"(ar0.y),"r"(ar1.y), "r"(b.x),"r"(b.y));
}
__device__ __forceinline__ void mma8v(float* d, uint4 a, unsigned b0, unsigned b1){
    asm volatile("mma.sync.aligned.m16n8k8.row.col.f32.tf32.tf32.f32 "
        "{%0,%1,%2,%3}, {%4,%5,%6,%7}, {%8,%9}, {%0,%1,%2,%3};"
        : "+f"(d[0]),"+f"(d[1]),"+f"(d[2]),"+f"(d[3])
        : "r"(a.x),"r"(a.y),"r"(a.z),"r"(a.w), "r"(b0),"r"(b1));
}
// fp16 m16n8k16: a02 = (a0,a2) one LDS.64 of row q; a13 = (a1,a3) of row q+8
__device__ __forceinline__ void mma16(float* d, uint2 a02, uint2 a13, uint2 b){
    asm volatile("mma.sync.aligned.m16n8k16.row.col.f32.f16.f16.f32 "
        "{%0,%1,%2,%3}, {%4,%5,%6,%7}, {%8,%9}, {%0,%1,%2,%3};"
        : "+f"(d[0]),"+f"(d[1]),"+f"(d[2]),"+f"(d[3])
        : "r"(a02.x),"r"(a13.x),"r"(a02.y),"r"(a13.y), "r"(b.x),"r"(b.y));
}
// interleave position of channel-in-group il (0..15): (2g,2g+1,2g+8,2g+9) contiguous
__device__ __forceinline__ int ipos16(int il){
    return (il < 8) ? ((il>>1)*4 + (il&1)) : (((il-8)>>1)*4 + 2 + (il&1));
}

// ---------------- bin indices ----------------
__device__ __forceinline__ int binof(float v){
    const float DEN = (float)(1.0 + 0.1 + 1e-6);
    float w = (v + 0.5f) / DEN;
    w = fminf(fmaxf(w, 0.0f), (float)(1.0 - 1e-6));
    return (int)(w * 64.0f);
}

__global__ void k_idx(const float* __restrict__ p){
    int i = blockIdx.x*256 + threadIdx.x;
    if(i >= BN) return;
    float x = p[i*3+0], y = p[i*3+1], z = p[i*3+2];
    int bx = binof(x), by = binof(y), bz = binof(z);
    g_idx[0*BN+i] = bx + 64*bz;
    g_idx[1*BN+i] = bx + 64*by;
    g_idx[2*BN+i] = by + 64*bz;
}

// ---------------- resblock weight prep (unchanged, tf32 pair-interleaved) ----------------
__global__ void k_wblk(const float* __restrict__ W0, const float* __restrict__ W1,
                       const float* __restrict__ Ws){
    int i = blockIdx.x*256 + threadIdx.x;
    if(i >= 3*20480) return;
    int m = i / 20480, r = i - m*20480;
    const float* src; int kc, e, K;
    if(r < 8192){ src = W0 + m*64*128; kc = r>>9; e = r&511; K = 128; }
    else if(r < 12288){ int q = r-8192; src = W1 + m*64*64; kc = q>>9; e = q&511; K = 64; }
    else { int q = r-12288; src = Ws + m*64*128; kc = q>>9; e = q&511; K = 128; }
    int wn = e>>8, ntp = (e>>7)&1, qn = (e>>4)&7, s = (e>>1)&7, g = e&1;
    int n = wn*32 + ntp*16 + g*8 + qn;
    int k = kc*8 + (s&1)*4 + (s>>1);
    g_wblk[i] = totf(src[n*K + k]);
}

// ---------------- fc_c weight prep ----------------
__global__ void k_wfcc(const float* __restrict__ Wc){
    int i = blockIdx.x*256 + threadIdx.x;
    if(i >= 16384) return;
    int s = i & 7, n = (i>>3)&255, kc = i>>11;
    int k = kc*8 + (s&1)*4 + (s>>1);
    g_wfcc[i] = totf(Wc[n*64 + k]);
}

// ---------------- fused resblock + scatter epilogue (unchanged from R11 best) ----------------
#define SM_BLOCK (8192*4)

__global__ void __launch_bounds__(256, 3) k_block(int mode, const float* __restrict__ p,
                        const float* __restrict__ fcW, const float* __restrict__ fcb,
                        const float* __restrict__ b0g, const float* __restrict__ b1g)
{
    extern __shared__ float sm[];
    float* x_s = sm;

    int t = threadIdx.x;
    int lane = t & 31, w = t >> 5;
    int wm = w & 3, wn = w >> 2;
    int q = lane >> 2, c = lane & 3;
    int s0 = (c < 2) ? 4*c     : 4*c - 7;
    int s1 = (c < 2) ? 4*c + 2 : 4*c - 5;

    int b = blockIdx.x / NT, tile = blockIdx.x % NT;
    int pt0 = tile*64;
    int npts = min(64, NP - pt0);
    int gbase = b*NP + pt0;

    const float* __restrict__ wg0 = g_wblk + mode*20480;
    const float* __restrict__ wg1 = wg0 + 8192;
    const float* __restrict__ wgs = wg0 + 12288;

    if(mode == 0){
        for(int e=t; e<2048; e+=256){
            int pt = e>>5, gg = e&31;
            int kc = gg>>1, half = gg&1;
            int kb = kc*8 + half*4;
            float* d = &x_s[kc*512 + (pt>>4)*128 + (pt&7)*16 + ((pt>>3)&1) + half*2];
            if(pt < npts){
                int gp = (gbase + pt)*3;
                float px = p[gp], py = p[gp+1], pz = p[gp+2];
                #pragma unroll
                for(int i2=0;i2<4;i2++){
                    int j = kb + i2;
                    float v = fcb[j] + px*fcW[j*3] + py*fcW[j*3+1] + pz*fcW[j*3+2];
                    d[4*i2] = totf(v);
                }
            } else {
                d[0]=0.f; d[4]=0.f; d[8]=0.f; d[12]=0.f;
            }
        }
    } else {
        const float* bs   = g_binsum2 + ((mode-1)&1)*(BATCH*R2*HID);
        const float* bcnt = g_bincnt2 + ((mode-1)&1)*(BATCH*R2);
        for(int e=t; e<2048; e+=256){
            int pt = e>>5, gg = e&31;
            int kc = gg>>1, half = gg&1;
            float4 v = make_float4(0.f,0.f,0.f,0.f);
            if(pt < npts){
                int gi = gbase + pt;
                if(kc < 8) v = *(const float4*)&g_net[gi*HID + kc*8 + half*4];
                else {
                    int row = b*R2 + g_idx[gi];
                    float inv = 1.0f / fmaxf(bcnt[row], 1.0f);
                    v = *(const float4*)&bs[row*HID + (kc-8)*8 + half*4];
                    v.x*=inv; v.y*=inv; v.z*=inv; v.w*=inv;
                }
            }
            float* d = &x_s[kc*512 + (pt>>4)*128 + (pt&7)*16 + ((pt>>3)&1) + half*2];
            d[0]=totf(v.x); d[4]=totf(v.y); d[8]=totf(v.z); d[12]=totf(v.w);
        }
    }
    __syncthreads();

    int rb = wm*16;
    int r0 = rb + q, r1 = rb + q + 8;
    int abase = wm*128 + q*16 + 4*c;
    int bbase = wn*256 + q*16 + 4*c;

    float aH[4][4], aS[4][4];
    #pragma unroll
    for(int nt=0;nt<4;nt++){
        aH[nt][0]=aH[nt][1]=aH[nt][2]=aH[nt][3]=0.f;
        aS[nt][0]=aS[nt][1]=aS[nt][2]=aS[nt][3]=0.f;
    }
    #pragma unroll 4
    for(int kc=0; kc<16; kc++){
        uint4 av = *(const uint4*)&x_s[kc*512 + abase];
        #pragma unroll
        for(int ntp=0; ntp<2; ntp++){
            uint4 w0v = *(const uint4*)&wg0[kc*512 + bbase + ntp*128];
            uint4 wsv = *(const uint4*)&wgs[kc*512 + bbase + ntp*128];
            mma8v(aH[2*ntp],   av, w0v.x, w0v.z);
            mma8v(aH[2*ntp+1], av, w0v.y, w0v.w);
            mma8v(aS[2*ntp],   av, wsv.x, wsv.z);
            mma8v(aS[2*ntp+1], av, wsv.y, wsv.w);
        }
    }
    __syncthreads();

    #pragma unroll
    for(int nt=0; nt<4; nt++){
        int j0 = wn*32 + nt*8 + 2*c;
        float2 bb = *(const float2*)&b0g[j0];
        float* dl = &x_s[(j0>>3)*512 + wm*128 + q*16];
        dl[s0*2 + 0] = totf(fmaxf(aH[nt][0]+bb.x, 0.f));
        dl[s1*2 + 0] = totf(fmaxf(aH[nt][1]+bb.y, 0.f));
        dl[s0*2 + 1] = totf(fmaxf(aH[nt][2]+bb.x, 0.f));
        dl[s1*2 + 1] = totf(fmaxf(aH[nt][3]+bb.y, 0.f));
    }
    __syncthreads();

    float aD[4][4];
    #pragma unroll
    for(int nt=0;nt<4;nt++){ aD[nt][0]=aD[nt][1]=aD[nt][2]=aD[nt][3]=0.f; }
    #pragma unroll
    for(int kc=0; kc<8; kc++){
        uint4 av = *(const uint4*)&x_s[kc*512 + abase];
        #pragma unroll
        for(int ntp=0; ntp<2; ntp++){
            uint4 wv = *(const uint4*)&wg1[kc*512 + bbase + ntp*128];
            mma8v(aD[2*ntp],   av, wv.x, wv.z);
            mma8v(aD[2*ntp+1], av, wv.y, wv.w);
        }
    }
    #pragma unroll
    for(int nt=0; nt<4; nt++){
        int j0 = wn*32 + nt*8 + 2*c;
        float2 bb = *(const float2*)&b1g[j0];
        aD[nt][0] = fmaxf(aD[nt][0]+bb.x, 0.f) + aS[nt][0];
        aD[nt][1] = fmaxf(aD[nt][1]+bb.y, 0.f) + aS[nt][1];
        aD[nt][2] = fmaxf(aD[nt][2]+bb.x, 0.f) + aS[nt][2];
        aD[nt][3] = fmaxf(aD[nt][3]+bb.y, 0.f) + aS[nt][3];
    }

    if(mode < 2){
        float* bs   = g_binsum2 + (mode&1)*(BATCH*R2*HID);
        float* bcnt = g_bincnt2 + (mode&1)*(BATCH*R2);
        if(wn==0 && c==0){
            if(r0 < npts) atomicAdd(&bcnt[b*R2 + g_idx[gbase+r0]], 1.0f);
            if(r1 < npts) atomicAdd(&bcnt[b*R2 + g_idx[gbase+r1]], 1.0f);
        }
        int bin0 = (r0 < npts) ? (b*R2 + g_idx[gbase+r0]) : -1;
        int bin1 = (r1 < npts) ? (b*R2 + g_idx[gbase+r1]) : -1;
        #pragma unroll
        for(int nt=0; nt<4; nt++){
            int j0 = wn*32 + nt*8 + 2*c;
            if(bin0 >= 0){
                *(float2*)&g_net[(gbase+r0)*HID + j0] = make_float2(aD[nt][0], aD[nt][1]);
                atomicAdd(&bs[bin0*HID + j0],   aD[nt][0]);
                atomicAdd(&bs[bin0*HID + j0+1], aD[nt][1]);
            }
            if(bin1 >= 0){
                *(float2*)&g_net[(gbase+r1)*HID + j0] = make_float2(aD[nt][2], aD[nt][3]);
                atomicAdd(&bs[bin1*HID + j0],   aD[nt][2]);
                atomicAdd(&bs[bin1*HID + j0+1], aD[nt][3]);
            }
        }
    } else {
        if(wn==0 && c==0){
            #pragma unroll
            for(int hh=0;hh<2;hh++){
                int r = rb + q + hh*8;
                if(r < npts){
                    int gi = gbase + r;
                    #pragma unroll
                    for(int pl=0;pl<3;pl++)
                        atomicAdd(&g_cnt3[(pl*BATCH+b)*R2 + g_idx[pl*BN+gi]], 1.0f);
                }
            }
        }
        int rowp[2][3];
        #pragma unroll
        for(int hh=0;hh<2;hh++){
            int r = rb + q + hh*8;
            if(r < npts){
                int gi = gbase + r;
                #pragma unroll
                for(int pl=0;pl<3;pl++)
                    rowp[hh][pl] = (pl*BATCH+b)*R2 + g_idx[pl*BN+gi];
            } else {
                rowp[hh][0]=rowp[hh][1]=rowp[hh][2]=-1;
            }
        }
        #pragma unroll
        for(int nt=0; nt<4; nt++){
            int j0 = wn*32 + nt*8 + 2*c;
            #pragma unroll
            for(int hh=0;hh<2;hh++){
                if(rowp[hh][0] >= 0){
                    float v0 = aD[nt][hh*2+0], v1 = aD[nt][hh*2+1];
                    #pragma unroll
                    for(int pl=0;pl<3;pl++){
                        atomicAdd(&g_nsum[rowp[hh][pl]*HID + j0],   v0);
                        atomicAdd(&g_nsum[rowp[hh][pl]*HID + j0+1], v1);
                    }
                }
            }
        }
    }
}

// ---------------- bin GEMM fc_c (TF32 mma) -> fp16 interleaved g_fea ----------------
#define SM_FCC ((4096 + 16384)*4)
__global__ void __launch_bounds__(256) k_fcc_bins(const float* __restrict__ bc){
    extern __shared__ float sm[];
    float* x_s = sm;
    float* w_s = sm + 4096;
    unsigned ws_u = (unsigned)__cvta_generic_to_shared(w_s);
    int t = threadIdx.x;
    int lane = t & 31, w = t >> 5;
    int wm = w & 1, wn = w >> 1;
    int q = lane >> 2, c = lane & 3;
    int r0b = blockIdx.x*64;

    for(int e=t; e<4096; e+=256)
        cpa(ws_u + (unsigned)e*16, g_wfcc + e*4, 16);
    CP_COMMIT;

    for(int e=t; e<1024; e+=256){
        int pt = e>>4, g = e&15;
        int kc = g>>1, half = g&1;
        int row = r0b + pt;
        float inv = 1.0f / fmaxf(g_cnt3[row], 1.0f);
        float4 v = *(const float4*)&g_nsum[row*HID + kc*8 + half*4];
        float* d = &x_s[kc*512 + pt*8 + half];
        d[0]=totf(v.x*inv); d[2]=totf(v.y*inv); d[4]=totf(v.z*inv); d[6]=totf(v.w*inv);
    }
    CP_WAIT0;
    __syncthreads();

    int rb = wm*32;
    float acc[2][8][4];
    #pragma unroll
    for(int mt=0;mt<2;mt++)
        #pragma unroll
        for(int nt=0;nt<8;nt++){ acc[mt][nt][0]=acc[mt][nt][1]=acc[mt][nt][2]=acc[mt][nt][3]=0.f; }
    #pragma unroll
    for(int kc=0; kc<8; kc++){
        uint2 a[2][2];
        #pragma unroll
        for(int mt=0;mt<2;mt++){
            a[mt][0] = *(const uint2*)&x_s[kc*512 + (rb+mt*16+q)*8 + 2*c];
            a[mt][1] = *(const uint2*)&x_s[kc*512 + (rb+mt*16+q+8)*8 + 2*c];
        }
        const float* wb = &w_s[kc*2048 + (wn*64 + q)*8 + 2*c];
        #pragma unroll
        for(int nt=0; nt<8; nt++){
            uint2 bb = *(const uint2*)&wb[nt*64];
            mma8(acc[0][nt], a[0][0], a[0][1], bb);
            mma8(acc[1][nt], a[1][0], a[1][1], bb);
        }
    }

    #pragma unroll
    for(int nt=0; nt<8; nt++){
        int j0 = wn*64 + nt*8 + 2*c;
        float2 bb = *(const float2*)&bc[j0];
        int C = j0 >> 4;
        int pos = ipos16(j0 & 15);
        #pragma unroll
        for(int mt=0;mt<2;mt++){
            #pragma unroll
            for(int half=0; half<2; half++){
                int r = rb + mt*16 + q + half*8;
                int row = r0b + r;
                float gate = (g_cnt3[row] > 0.f) ? 1.f : 0.f;
                *(__half2*)&g_fea[row*FD + C*16 + pos] =
                    __floats2half2_rn(gate*(acc[mt][nt][half*2+0]+bb.x),
                                      gate*(acc[mt][nt][half*2+1]+bb.y));
            }
        }
    }
}

// ---------------- conv weight prep: fp16 [conv][ch16][kk][oc][16 interleaved] ----------------
__global__ void k_wtrans(const float* __restrict__ Wa, const float* __restrict__ Wb){
    int i = blockIdx.x*256 + threadIdx.x;
    if(i >= 2*589824) return;
    int cI = i / 589824;
    int rem = i - cI*589824;
    int ch = rem / 36864;
    int r2 = rem - ch*36864;
    int kk = r2 >> 12;            // /4096
    int r3 = r2 & 4095;
    int oc = r3 >> 4;
    int hpos = r3 & 15;
    int g = hpos >> 2, rr = hpos & 3;
    int il = (rr < 2) ? (2*g + rr) : (2*g + 8 + (rr-2));
    int ic = ch*16 + il;
    const float* W = cI ? Wb : Wa;
    g_wt[i] = __float2half(W[oc*2304 + ic*9 + kk]);
}

// ---------------- 3x3 conv 256->256, FP16 m16n8k16, cp.async, 128 oc/block, 2 CTA/SM ----------------
// smem: ibuf [2][528 pos][32B], wbuf [2][9 kk][128 oc][32B]
#define SM_CONV (2*16896 + 2*36864)

__global__ void __launch_bounds__(256, 2) k_conv(
        const __half* __restrict__ in, __half* __restrict__ outh,
        float* __restrict__ outf,
        const __half* __restrict__ wt, const float* __restrict__ bias, int permout)
{
    extern __shared__ float smf[];
    char* smc = (char*)smf;
    unsigned ib_u = (unsigned)__cvta_generic_to_shared(smc);
    unsigned wb_u = ib_u + 2*16896;
    int t = threadIdx.x;
    int lane = t & 31, w = t >> 5;
    int wm = w & 3, wn = w >> 2;
    int q = lane >> 2, c = lane & 3;

    int ocb = blockIdx.x & 1;
    int r = blockIdx.x >> 1;
    int rp = r & 31;
    int pb = r >> 5;
    const __half* inp = in + (size_t)pb*R2*FD;
    int y0 = rp*2;
    int px_base = wm*32;

    float acc[2][8][4];
    #pragma unroll
    for(int mt=0; mt<2; mt++)
        #pragma unroll
        for(int nt=0; nt<8; nt++){
            acc[mt][nt][0]=0.f; acc[mt][nt][1]=0.f; acc[mt][nt][2]=0.f; acc[mt][nt][3]=0.f;
        }

    auto stage = [&](int ch, int buf){
        for(int e=t; e<1056; e+=256){
            int pos = e>>1, hf = e&1;
            int rr = pos/66, cc = pos - rr*66;
            int yy = y0 + rr - 1, xx = cc - 1;
            bool ok = (yy >= 0 && yy < 64 && (unsigned)xx < 64u);
            const __half* src = inp + ((ok ? (yy*64+xx) : 0)*FD + ch*16 + hf*8);
            cpa(ib_u + (unsigned)(buf*16896 + pos*32 + hf*16), src, ok ? 16 : 0);
        }
        const __half* wsrc = wt + (size_t)ch*36864 + ocb*2048;
        for(int e=t; e<2304; e+=256){
            int kk = e>>8, rem = e&255;
            cpa(wb_u + (unsigned)(buf*36864 + kk*4096 + rem*16),
                wsrc + kk*4096 + rem*8, 16);
        }
        CP_COMMIT;
    };

    stage(0, 0);
    for(int ch=0; ch<16; ch++){
        int cur = ch & 1;
        CP_WAIT0;
        __syncthreads();
        if(ch < 15) stage(ch+1, 1-cur);
        const char* in_s = smc + cur*16896;
        const char* w_s  = smc + 2*16896 + cur*36864;
        #pragma unroll
        for(int kk=0; kk<9; kk++){
            int ky = kk/3, kx = kk - ky*3;
            uint2 a[2][2];
            #pragma unroll
            for(int mt=0; mt<2; mt++){
                int px0 = px_base + mt*16 + q;
                a[mt][0] = *(const uint2*)(in_s + (((px0>>6)+ky)*66 + (px0&63)+kx)*32 + 8*c);
                int px1 = px0 + 8;
                a[mt][1] = *(const uint2*)(in_s + (((px1>>6)+ky)*66 + (px1&63)+kx)*32 + 8*c);
            }
            const char* wb = w_s + kk*4096 + q*32 + 8*c + wn*64*32;
            #pragma unroll
            for(int nt=0; nt<8; nt++){
                uint2 b = *(const uint2*)(wb + nt*256);
                mma16(acc[0][nt], a[0][0], a[0][1], b);
                mma16(acc[1][nt], a[1][0], a[1][1], b);
            }
        }
        __syncthreads();
    }

    int o_base = ocb*128 + wn*64;
    #pragma unroll
    for(int nt=0; nt<8; nt++){
        int oc = o_base + nt*8 + 2*c;
        float2 bb = *(const float2*)&bias[oc];
        int C = oc >> 4;
        int pos = ipos16(oc & 15);
        #pragma unroll
        for(int mt=0; mt<2; mt++){
            #pragma unroll
            for(int half=0; half<2; half++){
                int px = px_base + mt*16 + q + half*8;
                int y = y0 + (px>>6), x = px&63;
                int row = pb*R2 + y*64 + x;
                float v0 = fmaxf(acc[mt][nt][half*2+0]+bb.x, 0.f);
                float v1 = fmaxf(acc[mt][nt][half*2+1]+bb.y, 0.f);
                if(permout){
                    *(__half2*)&outh[(size_t)row*FD + C*16 + pos] = __floats2half2_rn(v0, v1);
                } else {
                    *(float2*)&outf[(size_t)row*FD + oc] = make_float2(v0, v1);
                }
            }
        }
    }
}

// ---------------- bilinear grid sample over 3 planes, accumulate ----------------
__global__ void k_sample(const float* __restrict__ query, float* __restrict__ out){
    int gid = blockIdx.x*256 + threadIdx.x;
    int w = gid >> 5, lane = gid & 31;
    if(w >= BN) return;
    int b = w / NP;
    float q0 = query[w*3+0], q1 = query[w*3+1], q2 = query[w*3+2];
    float a0[4] = {0,0,0,0}, a1[4] = {0,0,0,0};
    #pragma unroll
    for(int pl=0; pl<3; pl++){
        float qa = (pl==2) ? q1 : q0;
        float qb = (pl==1) ? q1 : q2;
        float gx = qa*2.0f - 1.0f, gy = qb*2.0f - 1.0f;
        float x = ((gx + 1.0f)*64.0f - 1.0f)*0.5f;
        float y = ((gy + 1.0f)*64.0f - 1.0f)*0.5f;
        x = fminf(fmaxf(x, 0.0f), 63.0f);
        y = fminf(fmaxf(y, 0.0f), 63.0f);
        float x0f = floorf(x), y0f = floorf(y);
        int x0 = (int)x0f, y0 = (int)y0f;
        int x1 = min(x0+1, 63), y1 = min(y0+1, 63);
        float wx = x - x0f, wy = y - y0f;
        const float* f = &g_fec[(pl*BATCH + b)*R2*FD];
        float ww[4] = {(1.f-wx)*(1.f-wy), wx*(1.f-wy), (1.f-wx)*wy, wx*wy};
        int pix[4] = {y0*64+x0, y0*64+x1, y1*64+x0, y1*64+x1};
        #pragma unroll
        for(int tp=0; tp<4; tp++){
            const float* base = f + pix[tp]*FD;
            float4 v0 = *(const float4*)&base[lane*4];
            float4 v1 = *(const float4*)&base[128 + lane*4];
            float g = ww[tp];
            a0[0]+=g*v0.x; a0[1]+=g*v0.y; a0[2]+=g*v0.z; a0[3]+=g*v0.w;
            a1[0]+=g*v1.x; a1[1]+=g*v1.y; a1[2]+=g*v1.z; a1[3]+=g*v1.w;
        }
    }
    float* ob = &out[w*FD];
    *(float4*)&ob[lane*4]       = make_float4(a0[0],a0[1],a0[2],a0[3]);
    *(float4*)&ob[128+lane*4]   = make_float4(a1[0],a1[1],a1[2],a1[3]);
}

// ---------------- launch ----------------
extern "C" void kernel_launch(void* const* d_in, const int* in_sizes, int n_in,
                              void* d_out, int out_size)
{
    const float* p    = (const float*)d_in[0];
    const float* qry  = (const float*)d_in[1];
    const float* fcW  = (const float*)d_in[2];
    const float* fcb  = (const float*)d_in[3];
    const float* W0   = (const float*)d_in[4];
    const float* b0   = (const float*)d_in[5];
    const float* W1   = (const float*)d_in[6];
    const float* b1   = (const float*)d_in[7];
    const float* Ws   = (const float*)d_in[8];
    const float* Wc   = (const float*)d_in[9];
    const float* bc   = (const float*)d_in[10];
    const float* C1W  = (const float*)d_in[11];
    const float* C1b  = (const float*)d_in[12];
    const float* C2W  = (const float*)d_in[13];
    const float* C2b  = (const float*)d_in[14];
    float* out = (float*)d_out;

    cudaFuncSetAttribute(k_block,    cudaFuncAttributeMaxDynamicSharedMemorySize, SM_BLOCK);
    cudaFuncSetAttribute(k_fcc_bins, cudaFuncAttributeMaxDynamicSharedMemorySize, SM_FCC);
    cudaFuncSetAttribute(k_conv,     cudaFuncAttributeMaxDynamicSharedMemorySize, SM_CONV);

    void *binsum2_p, *bincnt2_p, *nsum_p, *cnt3_p, *fea_p, *feb_p, *fec_p, *wt_p;
    cudaGetSymbolAddress(&binsum2_p, g_binsum2);
    cudaGetSymbolAddress(&bincnt2_p, g_bincnt2);
    cudaGetSymbolAddress(&nsum_p,    g_nsum);
    cudaGetSymbolAddress(&cnt3_p,    g_cnt3);
    cudaGetSymbolAddress(&fea_p,     g_fea);
    cudaGetSymbolAddress(&feb_p,     g_feb);
    cudaGetSymbolAddress(&fec_p,     g_fec);
    cudaGetSymbolAddress(&wt_p,      g_wt);

    k_idx<<<(BN+255)/256, 256>>>(p);
    k_wblk<<<(3*20480+255)/256, 256>>>(W0, W1, Ws);

    cudaMemsetAsync(binsum2_p, 0, (size_t)2*BATCH*R2*HID*4);
    cudaMemsetAsync(bincnt2_p, 0, (size_t)2*BATCH*R2*4);
    cudaMemsetAsync(nsum_p,    0, (size_t)NBROW*HID*4);
    cudaMemsetAsync(cnt3_p,    0, (size_t)NBROW*4);

    k_block<<<BATCH*NT, 256, SM_BLOCK>>>(0, p, fcW, fcb, b0, b1);
    k_block<<<BATCH*NT, 256, SM_BLOCK>>>(1, p, fcW, fcb, b0 + HID, b1 + HID);
    k_block<<<BATCH*NT, 256, SM_BLOCK>>>(2, p, fcW, fcb, b0 + 2*HID, b1 + 2*HID);

    k_wfcc<<<16384/256, 256>>>(Wc);
    k_fcc_bins<<<NBROW/64, 256, SM_FCC>>>(bc);

    k_wtrans<<<(2*589824)/256, 256>>>(C1W, C2W);
    k_conv<<<12*32*2, 256, SM_CONV>>>((const __half*)fea_p, (__half*)feb_p, (float*)fec_p,
                                      (const __half*)wt_p,          C1b, 1);
    k_conv<<<12*32*2, 256, SM_CONV>>>((const __half*)feb_p, (__half*)fea_p, (float*)fec_p,
                                      (const __half*)wt_p + 589824, C2b, 0);

    k_sample<<<(BN*32)/256, 256>>>(qry, out);
}

// round 13
// speedup vs baseline: 1.8728x; 1.2205x over previous
#include <cuda_runtime.h>
#include <cuda_fp16.h>

#define BATCH 4
#define NP 30000
#define BN (BATCH*NP)
#define HID 64
#define FD 256
#define R2 4096
#define NT 469   /* ceil(NP/64) */
#define NBROW (3*BATCH*R2)

// ---------------- scratch (no allocation allowed) ----------------
__device__ float g_net[BN*HID];
__device__ int   g_idx[3*BN];
__device__ float g_binsum2[2*BATCH*R2*HID];
__device__ float g_bincnt2[2*BATCH*R2];
__device__ float g_nsum[NBROW*HID];
__device__ float g_cnt3[NBROW];
__device__ __align__(128) __half g_fea[NBROW*FD];    // conv1 in  (fp16 interleaved)
__device__ __align__(128) __half g_feb[NBROW*FD];    // conv1 out (fp16 interleaved)
__device__ __align__(128) __half g_fec[NBROW*FD];    // conv2 out (fp16 natural)
__device__ __align__(128) __half g_wt[2*589824];     // conv fp16 wt [conv][ch16][kk][oc][16 interleaved]
__device__ __align__(128) __half g_wblk[3*20480];    // resblock fp16 wt [mode]: w0[8kc][64n][16] | w1[4kc] | ws[8kc]
__device__ __align__(128) float g_wfcc[16384];       // fc_c tf32 wt [8kc][256n][8s]

// ---------------- helpers ----------------
__device__ __forceinline__ float totf(float x){
    unsigned u; asm("cvt.rna.tf32.f32 %0, %1;" : "=r"(u) : "f"(x));
    return __uint_as_float(u);
}
__device__ __forceinline__ void cpa(unsigned d, const void* s, int sz){
    asm volatile("cp.async.cg.shared.global [%0], [%1], 16, %2;" :: "r"(d), "l"(s), "r"(sz));
}
#define CP_COMMIT asm volatile("cp.async.commit_group;")
#define CP_WAIT0  asm volatile("cp.async.wait_group 0;")

__device__ __forceinline__ void mma8(float* d, uint2 ar0, uint2 ar1, uint2 b){
    asm volatile("mma.sync.aligned.m16n8k8.row.col.f32.tf32.tf32.f32 "
        "{%0,%1,%2,%3}, {%4,%5,%6,%7}, {%8,%9}, {%0,%1,%2,%3};"
        : "+f"(d[0]),"+f"(d[1]),"+f"(d[2]),"+f"(d[3])
        : "r"(ar0.x),"r"(ar1.x),"r"(ar0.y),"r"(ar1.y), "r"(b.x),"r"(b.y));
}
// fp16 m16n8k16: a02 = LDS.64 of row q (a0,a2); a13 = LDS.64 of row q+8 (a1,a3)
__device__ __forceinline__ void mma16(float* d, uint2 a02, uint2 a13, uint2 b){
    asm volatile("mma.sync.aligned.m16n8k16.row.col.f32.f16.f16.f32 "
        "{%0,%1,%2,%3}, {%4,%5,%6,%7}, {%8,%9}, {%0,%1,%2,%3};"
        : "+f"(d[0]),"+f"(d[1]),"+f"(d[2]),"+f"(d[3])
        : "r"(a02.x),"r"(a13.x),"r"(a02.y),"r"(a13.y), "r"(b.x),"r"(b.y));
}
// interleave position of channel-in-group il (0..15): (2g,2g+1,2g+8,2g+9) contiguous
__device__ __forceinline__ int ipos16(int il){
    return (il < 8) ? ((il>>1)*4 + (il&1)) : (((il-8)>>1)*4 + 2 + (il&1));
}
// position of EVEN il (pair start)
__device__ __forceinline__ int ppos16(int il){
    return (il < 8) ? il*2 : (il-8)*2 + 2;
}

// ---------------- bin indices ----------------
__device__ __forceinline__ int binof(float v){
    const float DEN = (float)(1.0 + 0.1 + 1e-6);
    float w = (v + 0.5f) / DEN;
    w = fminf(fmaxf(w, 0.0f), (float)(1.0 - 1e-6));
    return (int)(w * 64.0f);
}

__global__ void k_idx(const float* __restrict__ p){
    int i = blockIdx.x*256 + threadIdx.x;
    if(i >= BN) return;
    float x = p[i*3+0], y = p[i*3+1], z = p[i*3+2];
    int bx = binof(x), by = binof(y), bz = binof(z);
    g_idx[0*BN+i] = bx + 64*bz;
    g_idx[1*BN+i] = bx + 64*by;
    g_idx[2*BN+i] = by + 64*bz;
}

// ---------------- resblock weight prep: fp16 interleaved-16 ----------------
// per mode (20480 halves): [0,8192) W0 [8kc][64n][16]; [8192,12288) W1 [4kc][64n][16]; [12288,20480) Ws [8kc][64n][16]
__global__ void k_wblk(const float* __restrict__ W0, const float* __restrict__ W1,
                       const float* __restrict__ Ws){
    int i = blockIdx.x*256 + threadIdx.x;
    if(i >= 3*20480) return;
    int m = i / 20480, r = i - m*20480;
    const float* src; int kc, n, pos, K;
    if(r < 8192){ src = W0 + m*8192; kc = r>>10; n = (r>>4)&63; pos = r&15; K = 128; }
    else if(r < 12288){ int rr = r-8192; src = W1 + m*4096; kc = rr>>10; n = (rr>>4)&63; pos = rr&15; K = 64; }
    else { int rr = r-12288; src = Ws + m*8192; kc = rr>>10; n = (rr>>4)&63; pos = rr&15; K = 128; }
    int g = pos>>2, rrb = pos&3;
    int il = (rrb < 2) ? (2*g + rrb) : (2*g + 8 + (rrb-2));
    int k = kc*16 + il;
    g_wblk[i] = __float2half(src[n*K + k]);
}

// ---------------- fc_c weight prep ----------------
__global__ void k_wfcc(const float* __restrict__ Wc){
    int i = blockIdx.x*256 + threadIdx.x;
    if(i >= 16384) return;
    int s = i & 7, n = (i>>3)&255, kc = i>>11;
    int k = kc*8 + (s&1)*4 + (s>>1);
    g_wfcc[i] = totf(Wc[n*64 + k]);
}

// ---------------- fused resblock + scatter epilogue: FP16 m16n8k16, B via LDG, 3 CTA/SM ----------------
// x_s halves [8kc][64pt][16 interleaved] = 16KB; h aliases first 4 kc after pass 1
#define SM_BLOCK (8192*2)

__global__ void __launch_bounds__(256, 3) k_block(int mode, const float* __restrict__ p,
                        const float* __restrict__ fcW, const float* __restrict__ fcb,
                        const float* __restrict__ b0g, const float* __restrict__ b1g)
{
    extern __shared__ float sm[];
    char* xc = (char*)sm;

    int t = threadIdx.x;
    int lane = t & 31, w = t >> 5;
    int wm = w & 3, wn = w >> 2;
    int q = lane >> 2, c = lane & 3;

    int b = blockIdx.x / NT, tile = blockIdx.x % NT;
    int pt0 = tile*64;
    int npts = min(64, NP - pt0);
    int gbase = b*NP + pt0;

    const char* w0c = (const char*)(g_wblk + mode*20480);
    const char* w1c = w0c + 8192*2;
    const char* wsc = w0c + 12288*2;

    // stage x tile: 64 pt x 128 ch (fp16 interleaved)
    if(mode == 0){
        for(int e=t; e<4096; e+=256){
            int pt = e>>6, pg = e&63;
            int j = pg*2;
            int kc = j>>4, pos = ppos16(j&15);
            __half2* d = (__half2*)(xc + kc*2048 + pt*32 + pos*2);
            if(pt < npts){
                int gp = (gbase + pt)*3;
                float px = p[gp], py = p[gp+1], pz = p[gp+2];
                float v0 = fcb[j]   + px*fcW[j*3]   + py*fcW[j*3+1]   + pz*fcW[j*3+2];
                float v1 = fcb[j+1] + px*fcW[j*3+3] + py*fcW[j*3+4]   + pz*fcW[j*3+5];
                *d = __floats2half2_rn(v0, v1);
            } else {
                *d = __floats2half2_rn(0.f, 0.f);
            }
        }
    } else {
        const float* bs   = g_binsum2 + ((mode-1)&1)*(BATCH*R2*HID);
        const float* bcnt = g_bincnt2 + ((mode-1)&1)*(BATCH*R2);
        for(int e=t; e<2048; e+=256){
            int pt = e>>5, q4 = e&31;
            int j = q4*4;
            int kc = j>>4, il = j&15;
            int pos1 = ppos16(il), pos2 = ppos16(il+2);
            float4 v = make_float4(0.f,0.f,0.f,0.f);
            if(pt < npts){
                int gi = gbase + pt;
                if(j < 64) v = *(const float4*)&g_net[gi*HID + j];
                else {
                    int row = b*R2 + g_idx[gi];
                    float inv = 1.0f / fmaxf(bcnt[row], 1.0f);
                    v = *(const float4*)&bs[row*HID + (j-64)];
                    v.x*=inv; v.y*=inv; v.z*=inv; v.w*=inv;
                }
            }
            *(__half2*)(xc + kc*2048 + pt*32 + pos1*2) = __floats2half2_rn(v.x, v.y);
            *(__half2*)(xc + kc*2048 + pt*32 + pos2*2) = __floats2half2_rn(v.z, v.w);
        }
    }
    __syncthreads();

    int rb = wm*16;
    int r0 = rb + q, r1 = rb + q + 8;
    int aoff0 = r0*32 + c*8, aoff1 = r1*32 + c*8;

    // PASS 1 (fused): aH = x@W0^T ; aS = x@Ws^T
    float aH[4][4], aS[4][4];
    #pragma unroll
    for(int nt=0;nt<4;nt++){
        aH[nt][0]=aH[nt][1]=aH[nt][2]=aH[nt][3]=0.f;
        aS[nt][0]=aS[nt][1]=aS[nt][2]=aS[nt][3]=0.f;
    }
    #pragma unroll
    for(int kc=0; kc<8; kc++){
        uint2 aR0 = *(const uint2*)(xc + kc*2048 + aoff0);
        uint2 aR1 = *(const uint2*)(xc + kc*2048 + aoff1);
        #pragma unroll
        for(int nt=0; nt<4; nt++){
            int boff = (wn*32 + nt*8 + q)*32 + c*8;
            uint2 b0v = *(const uint2*)(w0c + kc*2048 + boff);
            uint2 bsv = *(const uint2*)(wsc + kc*2048 + boff);
            mma16(aH[nt], aR0, aR1, b0v);
            mma16(aS[nt], aR0, aR1, bsv);
        }
    }
    __syncthreads();   // pass-1 x_s reads complete

    // write h into x_s alias (first 4 kc), fp16 interleaved
    #pragma unroll
    for(int nt=0; nt<4; nt++){
        int j0 = wn*32 + nt*8 + 2*c;
        float2 bb = *(const float2*)&b0g[j0];
        int kc = j0>>4, pos = ppos16(j0&15);
        *(__half2*)(xc + kc*2048 + r0*32 + pos*2) =
            __floats2half2_rn(fmaxf(aH[nt][0]+bb.x, 0.f), fmaxf(aH[nt][1]+bb.y, 0.f));
        *(__half2*)(xc + kc*2048 + r1*32 + pos*2) =
            __floats2half2_rn(fmaxf(aH[nt][2]+bb.x, 0.f), fmaxf(aH[nt][3]+bb.y, 0.f));
    }
    __syncthreads();

    // PASS 2: aD = h @ W1^T
    float aD[4][4];
    #pragma unroll
    for(int nt=0;nt<4;nt++){ aD[nt][0]=aD[nt][1]=aD[nt][2]=aD[nt][3]=0.f; }
    #pragma unroll
    for(int kc=0; kc<4; kc++){
        uint2 aR0 = *(const uint2*)(xc + kc*2048 + aoff0);
        uint2 aR1 = *(const uint2*)(xc + kc*2048 + aoff1);
        #pragma unroll
        for(int nt=0; nt<4; nt++){
            int boff = (wn*32 + nt*8 + q)*32 + c*8;
            uint2 wv = *(const uint2*)(w1c + kc*2048 + boff);
            mma16(aD[nt], aR0, aR1, wv);
        }
    }
    #pragma unroll
    for(int nt=0; nt<4; nt++){
        int j0 = wn*32 + nt*8 + 2*c;
        float2 bb = *(const float2*)&b1g[j0];
        aD[nt][0] = fmaxf(aD[nt][0]+bb.x, 0.f) + aS[nt][0];
        aD[nt][1] = fmaxf(aD[nt][1]+bb.y, 0.f) + aS[nt][1];
        aD[nt][2] = fmaxf(aD[nt][2]+bb.x, 0.f) + aS[nt][2];
        aD[nt][3] = fmaxf(aD[nt][3]+bb.y, 0.f) + aS[nt][3];
    }

    // ---------------- epilogue (unchanged) ----------------
    if(mode < 2){
        float* bs   = g_binsum2 + (mode&1)*(BATCH*R2*HID);
        float* bcnt = g_bincnt2 + (mode&1)*(BATCH*R2);
        if(wn==0 && c==0){
            if(r0 < npts) atomicAdd(&bcnt[b*R2 + g_idx[gbase+r0]], 1.0f);
            if(r1 < npts) atomicAdd(&bcnt[b*R2 + g_idx[gbase+r1]], 1.0f);
        }
        int bin0 = (r0 < npts) ? (b*R2 + g_idx[gbase+r0]) : -1;
        int bin1 = (r1 < npts) ? (b*R2 + g_idx[gbase+r1]) : -1;
        #pragma unroll
        for(int nt=0; nt<4; nt++){
            int j0 = wn*32 + nt*8 + 2*c;
            if(bin0 >= 0){
                *(float2*)&g_net[(gbase+r0)*HID + j0] = make_float2(aD[nt][0], aD[nt][1]);
                atomicAdd(&bs[bin0*HID + j0],   aD[nt][0]);
                atomicAdd(&bs[bin0*HID + j0+1], aD[nt][1]);
            }
            if(bin1 >= 0){
                *(float2*)&g_net[(gbase+r1)*HID + j0] = make_float2(aD[nt][2], aD[nt][3]);
                atomicAdd(&bs[bin1*HID + j0],   aD[nt][2]);
                atomicAdd(&bs[bin1*HID + j0+1], aD[nt][3]);
            }
        }
    } else {
        if(wn==0 && c==0){
            #pragma unroll
            for(int hh=0;hh<2;hh++){
                int r = rb + q + hh*8;
                if(r < npts){
                    int gi = gbase + r;
                    #pragma unroll
                    for(int pl=0;pl<3;pl++)
                        atomicAdd(&g_cnt3[(pl*BATCH+b)*R2 + g_idx[pl*BN+gi]], 1.0f);
                }
            }
        }
        int rowp[2][3];
        #pragma unroll
        for(int hh=0;hh<2;hh++){
            int r = rb + q + hh*8;
            if(r < npts){
                int gi = gbase + r;
                #pragma unroll
                for(int pl=0;pl<3;pl++)
                    rowp[hh][pl] = (pl*BATCH+b)*R2 + g_idx[pl*BN+gi];
            } else {
                rowp[hh][0]=rowp[hh][1]=rowp[hh][2]=-1;
            }
        }
        #pragma unroll
        for(int nt=0; nt<4; nt++){
            int j0 = wn*32 + nt*8 + 2*c;
            #pragma unroll
            for(int hh=0;hh<2;hh++){
                if(rowp[hh][0] >= 0){
                    float v0 = aD[nt][hh*2+0], v1 = aD[nt][hh*2+1];
                    #pragma unroll
                    for(int pl=0;pl<3;pl++){
                        atomicAdd(&g_nsum[rowp[hh][pl]*HID + j0],   v0);
                        atomicAdd(&g_nsum[rowp[hh][pl]*HID + j0+1], v1);
                    }
                }
            }
        }
    }
}

// ---------------- bin GEMM fc_c (TF32 mma) -> fp16 interleaved g_fea ----------------
#define SM_FCC ((4096 + 16384)*4)
__global__ void __launch_bounds__(256) k_fcc_bins(const float* __restrict__ bc){
    extern __shared__ float sm[];
    float* x_s = sm;
    float* w_s = sm + 4096;
    unsigned ws_u = (unsigned)__cvta_generic_to_shared(w_s);
    int t = threadIdx.x;
    int lane = t & 31, w = t >> 5;
    int wm = w & 1, wn = w >> 1;
    int q = lane >> 2, c = lane & 3;
    int r0b = blockIdx.x*64;

    for(int e=t; e<4096; e+=256)
        cpa(ws_u + (unsigned)e*16, g_wfcc + e*4, 16);
    CP_COMMIT;

    for(int e=t; e<1024; e+=256){
        int pt = e>>4, g = e&15;
        int kc = g>>1, half = g&1;
        int row = r0b + pt;
        float inv = 1.0f / fmaxf(g_cnt3[row], 1.0f);
        float4 v = *(const float4*)&g_nsum[row*HID + kc*8 + half*4];
        float* d = &x_s[kc*512 + pt*8 + half];
        d[0]=totf(v.x*inv); d[2]=totf(v.y*inv); d[4]=totf(v.z*inv); d[6]=totf(v.w*inv);
    }
    CP_WAIT0;
    __syncthreads();

    int rb = wm*32;
    float acc[2][8][4];
    #pragma unroll
    for(int mt=0;mt<2;mt++)
        #pragma unroll
        for(int nt=0;nt<8;nt++){ acc[mt][nt][0]=acc[mt][nt][1]=acc[mt][nt][2]=acc[mt][nt][3]=0.f; }
    #pragma unroll
    for(int kc=0; kc<8; kc++){
        uint2 a[2][2];
        #pragma unroll
        for(int mt=0;mt<2;mt++){
            a[mt][0] = *(const uint2*)&x_s[kc*512 + (rb+mt*16+q)*8 + 2*c];
            a[mt][1] = *(const uint2*)&x_s[kc*512 + (rb+mt*16+q+8)*8 + 2*c];
        }
        const float* wb = &w_s[kc*2048 + (wn*64 + q)*8 + 2*c];
        #pragma unroll
        for(int nt=0; nt<8; nt++){
            uint2 bb = *(const uint2*)&wb[nt*64];
            mma8(acc[0][nt], a[0][0], a[0][1], bb);
            mma8(acc[1][nt], a[1][0], a[1][1], bb);
        }
    }

    #pragma unroll
    for(int nt=0; nt<8; nt++){
        int j0 = wn*64 + nt*8 + 2*c;
        float2 bb = *(const float2*)&bc[j0];
        int C = j0 >> 4;
        int pos = ipos16(j0 & 15);
        #pragma unroll
        for(int mt=0;mt<2;mt++){
            #pragma unroll
            for(int half=0; half<2; half++){
                int r = rb + mt*16 + q + half*8;
                int row = r0b + r;
                float gate = (g_cnt3[row] > 0.f) ? 1.f : 0.f;
                *(__half2*)&g_fea[row*FD + C*16 + pos] =
                    __floats2half2_rn(gate*(acc[mt][nt][half*2+0]+bb.x),
                                      gate*(acc[mt][nt][half*2+1]+bb.y));
            }
        }
    }
}

// ---------------- conv weight prep: fp16 [conv][ch16][kk][oc][16 interleaved] ----------------
__global__ void k_wtrans(const float* __restrict__ Wa, const float* __restrict__ Wb){
    int i = blockIdx.x*256 + threadIdx.x;
    if(i >= 2*589824) return;
    int cI = i / 589824;
    int rem = i - cI*589824;
    int ch = rem / 36864;
    int r2 = rem - ch*36864;
    int kk = r2 >> 12;
    int r3 = r2 & 4095;
    int oc = r3 >> 4;
    int hpos = r3 & 15;
    int g = hpos >> 2, rr = hpos & 3;
    int il = (rr < 2) ? (2*g + rr) : (2*g + 8 + (rr-2));
    int ic = ch*16 + il;
    const float* W = cI ? Wb : Wa;
    g_wt[i] = __float2half(W[oc*2304 + ic*9 + kk]);
}

// ---------------- 3x3 conv 256->256, FP16 m16n8k16, cp.async, 128 oc/block, 2 CTA/SM ----------------
#define SM_CONV (2*16896 + 2*36864)

__global__ void __launch_bounds__(256, 2) k_conv(
        const __half* __restrict__ in, __half* __restrict__ out,
        const __half* __restrict__ wt, const float* __restrict__ bias, int permout)
{
    extern __shared__ float smf[];
    char* smc = (char*)smf;
    unsigned ib_u = (unsigned)__cvta_generic_to_shared(smc);
    unsigned wb_u = ib_u + 2*16896;
    int t = threadIdx.x;
    int lane = t & 31, w = t >> 5;
    int wm = w & 3, wn = w >> 2;
    int q = lane >> 2, c = lane & 3;

    int ocb = blockIdx.x & 1;
    int r = blockIdx.x >> 1;
    int rp = r & 31;
    int pb = r >> 5;
    const __half* inp = in + (size_t)pb*R2*FD;
    int y0 = rp*2;
    int px_base = wm*32;

    float acc[2][8][4];
    #pragma unroll
    for(int mt=0; mt<2; mt++)
        #pragma unroll
        for(int nt=0; nt<8; nt++){
            acc[mt][nt][0]=0.f; acc[mt][nt][1]=0.f; acc[mt][nt][2]=0.f; acc[mt][nt][3]=0.f;
        }

    auto stage = [&](int ch, int buf){
        for(int e=t; e<1056; e+=256){
            int pos = e>>1, hf = e&1;
            int rr = pos/66, cc = pos - rr*66;
            int yy = y0 + rr - 1, xx = cc - 1;
            bool ok = (yy >= 0 && yy < 64 && (unsigned)xx < 64u);
            const __half* src = inp + ((ok ? (yy*64+xx) : 0)*FD + ch*16 + hf*8);
            cpa(ib_u + (unsigned)(buf*16896 + pos*32 + hf*16), src, ok ? 16 : 0);
        }
        const __half* wsrc = wt + (size_t)ch*36864 + ocb*2048;
        for(int e=t; e<2304; e+=256){
            int kk = e>>8, rem = e&255;
            cpa(wb_u + (unsigned)(buf*36864 + kk*4096 + rem*16),
                wsrc + kk*4096 + rem*8, 16);
        }
        CP_COMMIT;
    };

    stage(0, 0);
    for(int ch=0; ch<16; ch++){
        int cur = ch & 1;
        CP_WAIT0;
        __syncthreads();
        if(ch < 15) stage(ch+1, 1-cur);
        const char* in_s = smc + cur*16896;
        const char* w_s  = smc + 2*16896 + cur*36864;
        #pragma unroll
        for(int kk=0; kk<9; kk++){
            int ky = kk/3, kx = kk - ky*3;
            uint2 a[2][2];
            #pragma unroll
            for(int mt=0; mt<2; mt++){
                int px0 = px_base + mt*16 + q;
                a[mt][0] = *(const uint2*)(in_s + (((px0>>6)+ky)*66 + (px0&63)+kx)*32 + 8*c);
                int px1 = px0 + 8;
                a[mt][1] = *(const uint2*)(in_s + (((px1>>6)+ky)*66 + (px1&63)+kx)*32 + 8*c);
            }
            const char* wb = w_s + kk*4096 + q*32 + 8*c + wn*64*32;
            #pragma unroll
            for(int nt=0; nt<8; nt++){
                uint2 b = *(const uint2*)(wb + nt*256);
                mma16(acc[0][nt], a[0][0], a[0][1], b);
                mma16(acc[1][nt], a[1][0], a[1][1], b);
            }
        }
        __syncthreads();
    }

    int o_base = ocb*128 + wn*64;
    #pragma unroll
    for(int nt=0; nt<8; nt++){
        int oc = o_base + nt*8 + 2*c;
        float2 bb = *(const float2*)&bias[oc];
        int C = oc >> 4;
        int pos = ipos16(oc & 15);
        #pragma unroll
        for(int mt=0; mt<2; mt++){
            #pragma unroll
            for(int half=0; half<2; half++){
                int px = px_base + mt*16 + q + half*8;
                int y = y0 + (px>>6), x = px&63;
                int row = pb*R2 + y*64 + x;
                float v0 = fmaxf(acc[mt][nt][half*2+0]+bb.x, 0.f);
                float v1 = fmaxf(acc[mt][nt][half*2+1]+bb.y, 0.f);
                if(permout){
                    *(__half2*)&out[(size_t)row*FD + C*16 + pos] = __floats2half2_rn(v0, v1);
                } else {
                    *(__half2*)&out[(size_t)row*FD + oc] = __floats2half2_rn(v0, v1);
                }
            }
        }
    }
}

// ---------------- bilinear grid sample over 3 planes (fp16 features), accumulate ----------------
__global__ void k_sample(const float* __restrict__ query, float* __restrict__ out){
    int gid = blockIdx.x*256 + threadIdx.x;
    int w = gid >> 5, lane = gid & 31;
    if(w >= BN) return;
    int b = w / NP;
    float q0 = query[w*3+0], q1 = query[w*3+1], q2 = query[w*3+2];
    float acc[8] = {0,0,0,0,0,0,0,0};
    #pragma unroll
    for(int pl=0; pl<3; pl++){
        float qa = (pl==2) ? q1 : q0;
        float qb = (pl==1) ? q1 : q2;
        float gx = qa*2.0f - 1.0f, gy = qb*2.0f - 1.0f;
        float x = ((gx + 1.0f)*64.0f - 1.0f)*0.5f;
        float y = ((gy + 1.0f)*64.0f - 1.0f)*0.5f;
        x = fminf(fmaxf(x, 0.0f), 63.0f);
        y = fminf(fmaxf(y, 0.0f), 63.0f);
        float x0f = floorf(x), y0f = floorf(y);
        int x0 = (int)x0f, y0 = (int)y0f;
        int x1 = min(x0+1, 63), y1 = min(y0+1, 63);
        float wx = x - x0f, wy = y - y0f;
        const __half* f = g_fec + (size_t)(pl*BATCH + b)*R2*FD;
        float ww[4] = {(1.f-wx)*(1.f-wy), wx*(1.f-wy), (1.f-wx)*wy, wx*wy};
        int pix[4] = {y0*64+x0, y0*64+x1, y1*64+x0, y1*64+x1};
        #pragma unroll
        for(int tp=0; tp<4; tp++){
            const __half* base = f + pix[tp]*FD + lane*8;
            uint4 v = *(const uint4*)base;
            float g = ww[tp];
            float2 p0 = __half22float2(*(__half2*)&v.x);
            float2 p1 = __half22float2(*(__half2*)&v.y);
            float2 p2 = __half22float2(*(__half2*)&v.z);
            float2 p3 = __half22float2(*(__half2*)&v.w);
            acc[0]+=g*p0.x; acc[1]+=g*p0.y; acc[2]+=g*p1.x; acc[3]+=g*p1.y;
            acc[4]+=g*p2.x; acc[5]+=g*p2.y; acc[6]+=g*p3.x; acc[7]+=g*p3.y;
        }
    }
    float* ob = &out[w*FD + lane*8];
    *(float4*)&ob[0] = make_float4(acc[0],acc[1],acc[2],acc[3]);
    *(float4*)&ob[4] = make_float4(acc[4],acc[5],acc[6],acc[7]);
}

// ---------------- launch ----------------
extern "C" void kernel_launch(void* const* d_in, const int* in_sizes, int n_in,
                              void* d_out, int out_size)
{
    const float* p    = (const float*)d_in[0];
    const float* qry  = (const float*)d_in[1];
    const float* fcW  = (const float*)d_in[2];
    const float* fcb  = (const float*)d_in[3];
    const float* W0   = (const float*)d_in[4];
    const float* b0   = (const float*)d_in[5];
    const float* W1   = (const float*)d_in[6];
    const float* b1   = (const float*)d_in[7];
    const float* Ws   = (const float*)d_in[8];
    const float* Wc   = (const float*)d_in[9];
    const float* bc   = (const float*)d_in[10];
    const float* C1W  = (const float*)d_in[11];
    const float* C1b  = (const float*)d_in[12];
    const float* C2W  = (const float*)d_in[13];
    const float* C2b  = (const float*)d_in[14];
    float* out = (float*)d_out;

    cudaFuncSetAttribute(k_block,    cudaFuncAttributeMaxDynamicSharedMemorySize, SM_BLOCK);
    cudaFuncSetAttribute(k_fcc_bins, cudaFuncAttributeMaxDynamicSharedMemorySize, SM_FCC);
    cudaFuncSetAttribute(k_conv,     cudaFuncAttributeMaxDynamicSharedMemorySize, SM_CONV);

    void *binsum2_p, *bincnt2_p, *nsum_p, *cnt3_p, *fea_p, *feb_p, *fec_p, *wt_p;
    cudaGetSymbolAddress(&binsum2_p, g_binsum2);
    cudaGetSymbolAddress(&bincnt2_p, g_bincnt2);
    cudaGetSymbolAddress(&nsum_p,    g_nsum);
    cudaGetSymbolAddress(&cnt3_p,    g_cnt3);
    cudaGetSymbolAddress(&fea_p,     g_fea);
    cudaGetSymbolAddress(&feb_p,     g_feb);
    cudaGetSymbolAddress(&fec_p,     g_fec);
    cudaGetSymbolAddress(&wt_p,      g_wt);

    k_idx<<<(BN+255)/256, 256>>>(p);
    k_wblk<<<(3*20480+255)/256, 256>>>(W0, W1, Ws);

    cudaMemsetAsync(binsum2_p, 0, (size_t)2*BATCH*R2*HID*4);
    cudaMemsetAsync(bincnt2_p, 0, (size_t)2*BATCH*R2*4);
    cudaMemsetAsync(nsum_p,    0, (size_t)NBROW*HID*4);
    cudaMemsetAsync(cnt3_p,    0, (size_t)NBROW*4);

    k_block<<<BATCH*NT, 256, SM_BLOCK>>>(0, p, fcW, fcb, b0, b1);
    k_block<<<BATCH*NT, 256, SM_BLOCK>>>(1, p, fcW, fcb, b0 + HID, b1 + HID);
    k_block<<<BATCH*NT, 256, SM_BLOCK>>>(2, p, fcW, fcb, b0 + 2*HID, b1 + 2*HID);

    k_wfcc<<<16384/256, 256>>>(Wc);
    k_fcc_bins<<<NBROW/64, 256, SM_FCC>>>(bc);

    k_wtrans<<<(2*589824)/256, 256>>>(C1W, C2W);
    k_conv<<<12*32*2, 256, SM_CONV>>>((const __half*)fea_p, (__half*)feb_p,
                                      (const __half*)wt_p,          C1b, 1);
    k_conv<<<12*32*2, 256, SM_CONV>>>((const __half*)feb_p, (__half*)fec_p,
                                      (const __half*)wt_p + 589824, C2b, 0);

    k_sample<<<(BN*32)/256, 256>>>(qry, out);
}

// round 14
// speedup vs baseline: 1.8974x; 1.0131x over previous
#include <cuda_runtime.h>
#include <cuda_fp16.h>

#define BATCH 4
#define NP 30000
#define BN (BATCH*NP)
#define HID 64
#define FD 256
#define R2 4096
#define NT 469   /* ceil(NP/64) */
#define NBROW (3*BATCH*R2)

// ---------------- scratch (no allocation allowed) ----------------
__device__ float g_net[BN*HID];
__device__ int   g_idx[3*BN];
// single zero-init region: binsum2 | bincnt2 | nsum | cnt3
#define ZFLOATS (2*BATCH*R2*HID + 2*BATCH*R2 + NBROW*HID + NBROW)
__device__ float g_zeros[ZFLOATS];
#define G_BINSUM2 (g_zeros)
#define G_BINCNT2 (g_zeros + 2*BATCH*R2*HID)
#define G_NSUM    (g_zeros + 2*BATCH*R2*HID + 2*BATCH*R2)
#define G_CNT3    (g_zeros + 2*BATCH*R2*HID + 2*BATCH*R2 + NBROW*HID)
__device__ __align__(128) __half g_fea[NBROW*FD];    // conv1 in  (fp16 interleaved)
__device__ __align__(128) __half g_feb[NBROW*FD];    // conv1 out (fp16 interleaved)
__device__ __align__(128) __half g_fec[NBROW*FD];    // conv2 out (fp16 natural)
__device__ __align__(128) __half g_wt[2*589824];     // conv fp16 wt [conv][ch16][kk][oc][16 interleaved]
__device__ __align__(128) __half g_wblk[3*20480];    // resblock fp16 wt
__device__ __align__(128) float g_wfcc[16384];       // fc_c tf32 wt [8kc][256n][8s]

// ---------------- helpers ----------------
__device__ __forceinline__ float totf(float x){
    unsigned u; asm("cvt.rna.tf32.f32 %0, %1;" : "=r"(u) : "f"(x));
    return __uint_as_float(u);
}
__device__ __forceinline__ void cpa(unsigned d, const void* s, int sz){
    asm volatile("cp.async.cg.shared.global [%0], [%1], 16, %2;" :: "r"(d), "l"(s), "r"(sz));
}
#define CP_COMMIT asm volatile("cp.async.commit_group;")
#define CP_WAIT0  asm volatile("cp.async.wait_group 0;")

__device__ __forceinline__ void mma8(float* d, uint2 ar0, uint2 ar1, uint2 b){
    asm volatile("mma.sync.aligned.m16n8k8.row.col.f32.tf32.tf32.f32 "
        "{%0,%1,%2,%3}, {%4,%5,%6,%7}, {%8,%9}, {%0,%1,%2,%3};"
        : "+f"(d[0]),"+f"(d[1]),"+f"(d[2]),"+f"(d[3])
        : "r"(ar0.x),"r"(ar1.x),"r"(ar0.y),"r"(ar1.y), "r"(b.x),"r"(b.y));
}
__device__ __forceinline__ void mma16(float* d, uint2 a02, uint2 a13, uint2 b){
    asm volatile("mma.sync.aligned.m16n8k16.row.col.f32.f16.f16.f32 "
        "{%0,%1,%2,%3}, {%4,%5,%6,%7}, {%8,%9}, {%0,%1,%2,%3};"
        : "+f"(d[0]),"+f"(d[1]),"+f"(d[2]),"+f"(d[3])
        : "r"(a02.x),"r"(a13.x),"r"(a02.y),"r"(a13.y), "r"(b.x),"r"(b.y));
}
__device__ __forceinline__ int ipos16(int il){
    return (il < 8) ? ((il>>1)*4 + (il&1)) : (((il-8)>>1)*4 + 2 + (il&1));
}
__device__ __forceinline__ int ppos16(int il){
    return (il < 8) ? il*2 : (il-8)*2 + 2;
}
__device__ __forceinline__ int binof(float v){
    const float DEN = (float)(1.0 + 0.1 + 1e-6);
    float w = (v + 0.5f) / DEN;
    w = fminf(fmaxf(w, 0.0f), (float)(1.0 - 1e-6));
    return (int)(w * 64.0f);
}

// ---------------- merged prep: idx | wblk | wfcc | wtrans ----------------
#define PREP_TOTAL (BN + 3*20480 + 16384 + 2*589824)
__global__ void k_prep(const float* __restrict__ p,
                       const float* __restrict__ W0, const float* __restrict__ W1,
                       const float* __restrict__ Ws, const float* __restrict__ Wc,
                       const float* __restrict__ C1W, const float* __restrict__ C2W){
    int i = blockIdx.x*256 + threadIdx.x;
    if(i < BN){
        float x = p[i*3+0], y = p[i*3+1], z = p[i*3+2];
        int bx = binof(x), by = binof(y), bz = binof(z);
        g_idx[0*BN+i] = bx + 64*bz;
        g_idx[1*BN+i] = bx + 64*by;
        g_idx[2*BN+i] = by + 64*bz;
        return;
    }
    i -= BN;
    if(i < 3*20480){
        int m = i / 20480, r = i - m*20480;
        const float* src; int kc, n, pos, K;
        if(r < 8192){ src = W0 + m*8192; kc = r>>10; n = (r>>4)&63; pos = r&15; K = 128; }
        else if(r < 12288){ int rr = r-8192; src = W1 + m*4096; kc = rr>>10; n = (rr>>4)&63; pos = rr&15; K = 64; }
        else { int rr = r-12288; src = Ws + m*8192; kc = rr>>10; n = (rr>>4)&63; pos = rr&15; K = 128; }
        int g = pos>>2, rrb = pos&3;
        int il = (rrb < 2) ? (2*g + rrb) : (2*g + 8 + (rrb-2));
        int k = kc*16 + il;
        g_wblk[i] = __float2half(src[n*K + k]);
        return;
    }
    i -= 3*20480;
    if(i < 16384){
        int s = i & 7, n = (i>>3)&255, kc = i>>11;
        int k = kc*8 + (s&1)*4 + (s>>1);
        g_wfcc[i] = totf(Wc[n*64 + k]);
        return;
    }
    i -= 16384;
    if(i < 2*589824){
        int cI = i / 589824;
        int rem = i - cI*589824;
        int ch = rem / 36864;
        int r2 = rem - ch*36864;
        int kk = r2 >> 12;
        int r3 = r2 & 4095;
        int oc = r3 >> 4;
        int hpos = r3 & 15;
        int g = hpos >> 2, rr = hpos & 3;
        int il = (rr < 2) ? (2*g + rr) : (2*g + 8 + (rr-2));
        int ic = ch*16 + il;
        const float* W = cI ? C2W : C1W;
        g_wt[i] = __float2half(W[oc*2304 + ic*9 + kk]);
    }
}

// ---------------- fused resblock + scatter epilogue: FP16 m16n8k16, 4 CTA/SM target ----------------
// smem: x_s [8kc][64pt][32B] = 16KB at 0; h_s [4kc][64pt][32B] = 8KB at 16384
#define SM_BLOCK (24576)

__global__ void __launch_bounds__(256, 4) k_block(int mode, const float* __restrict__ p,
                        const float* __restrict__ fcW, const float* __restrict__ fcb,
                        const float* __restrict__ b0g, const float* __restrict__ b1g)
{
    extern __shared__ float sm[];
    char* xc = (char*)sm;
    char* hc = xc + 16384;

    int t = threadIdx.x;
    int lane = t & 31, w = t >> 5;
    int wm = w & 3, wn = w >> 2;
    int q = lane >> 2, c = lane & 3;

    int b = blockIdx.x / NT, tile = blockIdx.x % NT;
    int pt0 = tile*64;
    int npts = min(64, NP - pt0);
    int gbase = b*NP + pt0;

    const char* w0c = (const char*)(g_wblk + mode*20480);
    const char* w1c = w0c + 8192*2;
    const char* wsc = w0c + 12288*2;

    // stage x tile: 64 pt x 128 ch (fp16 interleaved)
    if(mode == 0){
        for(int e=t; e<4096; e+=256){
            int pt = e>>6, pg = e&63;
            int j = pg*2;
            int kc = j>>4, pos = ppos16(j&15);
            __half2* d = (__half2*)(xc + kc*2048 + pt*32 + pos*2);
            if(pt < npts){
                int gp = (gbase + pt)*3;
                float px = p[gp], py = p[gp+1], pz = p[gp+2];
                float v0 = fcb[j]   + px*fcW[j*3]   + py*fcW[j*3+1]   + pz*fcW[j*3+2];
                float v1 = fcb[j+1] + px*fcW[j*3+3] + py*fcW[j*3+4]   + pz*fcW[j*3+5];
                *d = __floats2half2_rn(v0, v1);
            } else {
                *d = __floats2half2_rn(0.f, 0.f);
            }
        }
    } else {
        const float* bs   = G_BINSUM2 + ((mode-1)&1)*(BATCH*R2*HID);
        const float* bcnt = G_BINCNT2 + ((mode-1)&1)*(BATCH*R2);
        for(int e=t; e<2048; e+=256){
            int pt = e>>5, q4 = e&31;
            int j = q4*4;
            int kc = j>>4, il = j&15;
            int pos1 = ppos16(il), pos2 = ppos16(il+2);
            float4 v = make_float4(0.f,0.f,0.f,0.f);
            if(pt < npts){
                int gi = gbase + pt;
                if(j < 64) v = *(const float4*)&g_net[gi*HID + j];
                else {
                    int row = b*R2 + g_idx[gi];
                    float inv = 1.0f / fmaxf(bcnt[row], 1.0f);
                    v = *(const float4*)&bs[row*HID + (j-64)];
                    v.x*=inv; v.y*=inv; v.z*=inv; v.w*=inv;
                }
            }
            *(__half2*)(xc + kc*2048 + pt*32 + pos1*2) = __floats2half2_rn(v.x, v.y);
            *(__half2*)(xc + kc*2048 + pt*32 + pos2*2) = __floats2half2_rn(v.z, v.w);
        }
    }
    __syncthreads();

    int rb = wm*16;
    int r0 = rb + q, r1 = rb + q + 8;
    int aoff0 = r0*32 + c*8, aoff1 = r1*32 + c*8;

    // PASS 1 (fused): aH = x@W0^T ; aS = x@Ws^T
    float aH[4][4], aS[4][4];
    #pragma unroll
    for(int nt=0;nt<4;nt++){
        aH[nt][0]=aH[nt][1]=aH[nt][2]=aH[nt][3]=0.f;
        aS[nt][0]=aS[nt][1]=aS[nt][2]=aS[nt][3]=0.f;
    }
    #pragma unroll
    for(int kc=0; kc<8; kc++){
        uint2 aR0 = *(const uint2*)(xc + kc*2048 + aoff0);
        uint2 aR1 = *(const uint2*)(xc + kc*2048 + aoff1);
        #pragma unroll
        for(int nt=0; nt<4; nt++){
            int boff = (wn*32 + nt*8 + q)*32 + c*8;
            uint2 b0v = *(const uint2*)(w0c + kc*2048 + boff);
            uint2 bsv = *(const uint2*)(wsc + kc*2048 + boff);
            mma16(aH[nt], aR0, aR1, b0v);
            mma16(aS[nt], aR0, aR1, bsv);
        }
    }

    // write h into separate h buffer (no WAR sync needed)
    #pragma unroll
    for(int nt=0; nt<4; nt++){
        int j0 = wn*32 + nt*8 + 2*c;
        float2 bb = *(const float2*)&b0g[j0];
        int kc = j0>>4, pos = ppos16(j0&15);
        *(__half2*)(hc + kc*2048 + r0*32 + pos*2) =
            __floats2half2_rn(fmaxf(aH[nt][0]+bb.x, 0.f), fmaxf(aH[nt][1]+bb.y, 0.f));
        *(__half2*)(hc + kc*2048 + r1*32 + pos*2) =
            __floats2half2_rn(fmaxf(aH[nt][2]+bb.x, 0.f), fmaxf(aH[nt][3]+bb.y, 0.f));
    }
    __syncthreads();

    // PASS 2: aD = h @ W1^T
    float aD[4][4];
    #pragma unroll
    for(int nt=0;nt<4;nt++){ aD[nt][0]=aD[nt][1]=aD[nt][2]=aD[nt][3]=0.f; }
    #pragma unroll
    for(int kc=0; kc<4; kc++){
        uint2 aR0 = *(const uint2*)(hc + kc*2048 + aoff0);
        uint2 aR1 = *(const uint2*)(hc + kc*2048 + aoff1);
        #pragma unroll
        for(int nt=0; nt<4; nt++){
            int boff = (wn*32 + nt*8 + q)*32 + c*8;
            uint2 wv = *(const uint2*)(w1c + kc*2048 + boff);
            mma16(aD[nt], aR0, aR1, wv);
        }
    }
    #pragma unroll
    for(int nt=0; nt<4; nt++){
        int j0 = wn*32 + nt*8 + 2*c;
        float2 bb = *(const float2*)&b1g[j0];
        aD[nt][0] = fmaxf(aD[nt][0]+bb.x, 0.f) + aS[nt][0];
        aD[nt][1] = fmaxf(aD[nt][1]+bb.y, 0.f) + aS[nt][1];
        aD[nt][2] = fmaxf(aD[nt][2]+bb.x, 0.f) + aS[nt][2];
        aD[nt][3] = fmaxf(aD[nt][3]+bb.y, 0.f) + aS[nt][3];
    }

    // ---------------- epilogue ----------------
    if(mode < 2){
        float* bs   = G_BINSUM2 + (mode&1)*(BATCH*R2*HID);
        float* bcnt = G_BINCNT2 + (mode&1)*(BATCH*R2);
        if(wn==0 && c==0){
            if(r0 < npts) atomicAdd(&bcnt[b*R2 + g_idx[gbase+r0]], 1.0f);
            if(r1 < npts) atomicAdd(&bcnt[b*R2 + g_idx[gbase+r1]], 1.0f);
        }
        int bin0 = (r0 < npts) ? (b*R2 + g_idx[gbase+r0]) : -1;
        int bin1 = (r1 < npts) ? (b*R2 + g_idx[gbase+r1]) : -1;
        #pragma unroll
        for(int nt=0; nt<4; nt++){
            int j0 = wn*32 + nt*8 + 2*c;
            if(bin0 >= 0){
                *(float2*)&g_net[(gbase+r0)*HID + j0] = make_float2(aD[nt][0], aD[nt][1]);
                atomicAdd(&bs[bin0*HID + j0],   aD[nt][0]);
                atomicAdd(&bs[bin0*HID + j0+1], aD[nt][1]);
            }
            if(bin1 >= 0){
                *(float2*)&g_net[(gbase+r1)*HID + j0] = make_float2(aD[nt][2], aD[nt][3]);
                atomicAdd(&bs[bin1*HID + j0],   aD[nt][2]);
                atomicAdd(&bs[bin1*HID + j0+1], aD[nt][3]);
            }
        }
    } else {
        if(wn==0 && c==0){
            #pragma unroll
            for(int hh=0;hh<2;hh++){
                int r = rb + q + hh*8;
                if(r < npts){
                    int gi = gbase + r;
                    #pragma unroll
                    for(int pl=0;pl<3;pl++)
                        atomicAdd(&G_CNT3[(pl*BATCH+b)*R2 + g_idx[pl*BN+gi]], 1.0f);
                }
            }
        }
        int rowp[2][3];
        #pragma unroll
        for(int hh=0;hh<2;hh++){
            int r = rb + q + hh*8;
            if(r < npts){
                int gi = gbase + r;
                #pragma unroll
                for(int pl=0;pl<3;pl++)
                    rowp[hh][pl] = (pl*BATCH+b)*R2 + g_idx[pl*BN+gi];
            } else {
                rowp[hh][0]=rowp[hh][1]=rowp[hh][2]=-1;
            }
        }
        #pragma unroll
        for(int nt=0; nt<4; nt++){
            int j0 = wn*32 + nt*8 + 2*c;
            #pragma unroll
            for(int hh=0;hh<2;hh++){
                if(rowp[hh][0] >= 0){
                    float v0 = aD[nt][hh*2+0], v1 = aD[nt][hh*2+1];
                    #pragma unroll
                    for(int pl=0;pl<3;pl++){
                        atomicAdd(&G_NSUM[rowp[hh][pl]*HID + j0],   v0);
                        atomicAdd(&G_NSUM[rowp[hh][pl]*HID + j0+1], v1);
                    }
                }
            }
        }
    }
}

// ---------------- bin GEMM fc_c (TF32 mma) -> fp16 interleaved g_fea ----------------
#define SM_FCC ((4096 + 16384)*4)
__global__ void __launch_bounds__(256) k_fcc_bins(const float* __restrict__ bc){
    extern __shared__ float sm[];
    float* x_s = sm;
    float* w_s = sm + 4096;
    unsigned ws_u = (unsigned)__cvta_generic_to_shared(w_s);
    int t = threadIdx.x;
    int lane = t & 31, w = t >> 5;
    int wm = w & 1, wn = w >> 1;
    int q = lane >> 2, c = lane & 3;
    int r0b = blockIdx.x*64;

    for(int e=t; e<4096; e+=256)
        cpa(ws_u + (unsigned)e*16, g_wfcc + e*4, 16);
    CP_COMMIT;

    for(int e=t; e<1024; e+=256){
        int pt = e>>4, g = e&15;
        int kc = g>>1, half = g&1;
        int row = r0b + pt;
        float inv = 1.0f / fmaxf(G_CNT3[row], 1.0f);
        float4 v = *(const float4*)&G_NSUM[row*HID + kc*8 + half*4];
        float* d = &x_s[kc*512 + pt*8 + half];
        d[0]=totf(v.x*inv); d[2]=totf(v.y*inv); d[4]=totf(v.z*inv); d[6]=totf(v.w*inv);
    }
    CP_WAIT0;
    __syncthreads();

    int rb = wm*32;
    float acc[2][8][4];
    #pragma unroll
    for(int mt=0;mt<2;mt++)
        #pragma unroll
        for(int nt=0;nt<8;nt++){ acc[mt][nt][0]=acc[mt][nt][1]=acc[mt][nt][2]=acc[mt][nt][3]=0.f; }
    #pragma unroll
    for(int kc=0; kc<8; kc++){
        uint2 a[2][2];
        #pragma unroll
        for(int mt=0;mt<2;mt++){
            a[mt][0] = *(const uint2*)&x_s[kc*512 + (rb+mt*16+q)*8 + 2*c];
            a[mt][1] = *(const uint2*)&x_s[kc*512 + (rb+mt*16+q+8)*8 + 2*c];
        }
        const float* wb = &w_s[kc*2048 + (wn*64 + q)*8 + 2*c];
        #pragma unroll
        for(int nt=0; nt<8; nt++){
            uint2 bb = *(const uint2*)&wb[nt*64];
            mma8(acc[0][nt], a[0][0], a[0][1], bb);
            mma8(acc[1][nt], a[1][0], a[1][1], bb);
        }
    }

    #pragma unroll
    for(int nt=0; nt<8; nt++){
        int j0 = wn*64 + nt*8 + 2*c;
        float2 bb = *(const float2*)&bc[j0];
        int C = j0 >> 4;
        int pos = ipos16(j0 & 15);
        #pragma unroll
        for(int mt=0;mt<2;mt++){
            #pragma unroll
            for(int half=0; half<2; half++){
                int r = rb + mt*16 + q + half*8;
                int row = r0b + r;
                float gate = (G_CNT3[row] > 0.f) ? 1.f : 0.f;
                *(__half2*)&g_fea[row*FD + C*16 + pos] =
                    __floats2half2_rn(gate*(acc[mt][nt][half*2+0]+bb.x),
                                      gate*(acc[mt][nt][half*2+1]+bb.y));
            }
        }
    }
}

// ---------------- 3x3 conv 256->256, FP16 m16n8k16, cp.async, 128 oc/block, 2 CTA/SM ----------------
#define SM_CONV (2*16896 + 2*36864)

__global__ void __launch_bounds__(256, 2) k_conv(
        const __half* __restrict__ in, __half* __restrict__ out,
        const __half* __restrict__ wt, const float* __restrict__ bias, int permout)
{
    extern __shared__ float smf[];
    char* smc = (char*)smf;
    unsigned ib_u = (unsigned)__cvta_generic_to_shared(smc);
    unsigned wb_u = ib_u + 2*16896;
    int t = threadIdx.x;
    int lane = t & 31, w = t >> 5;
    int wm = w & 3, wn = w >> 2;
    int q = lane >> 2, c = lane & 3;

    int ocb = blockIdx.x & 1;
    int r = blockIdx.x >> 1;
    int rp = r & 31;
    int pb = r >> 5;
    const __half* inp = in + (size_t)pb*R2*FD;
    int y0 = rp*2;
    int px_base = wm*32;

    float acc[2][8][4];
    #pragma unroll
    for(int mt=0; mt<2; mt++)
        #pragma unroll
        for(int nt=0; nt<8; nt++){
            acc[mt][nt][0]=0.f; acc[mt][nt][1]=0.f; acc[mt][nt][2]=0.f; acc[mt][nt][3]=0.f;
        }

    auto stage = [&](int ch, int buf){
        for(int e=t; e<1056; e+=256){
            int pos = e>>1, hf = e&1;
            int rr = pos/66, cc = pos - rr*66;
            int yy = y0 + rr - 1, xx = cc - 1;
            bool ok = (yy >= 0 && yy < 64 && (unsigned)xx < 64u);
            const __half* src = inp + ((ok ? (yy*64+xx) : 0)*FD + ch*16 + hf*8);
            cpa(ib_u + (unsigned)(buf*16896 + pos*32 + hf*16), src, ok ? 16 : 0);
        }
        const __half* wsrc = wt + (size_t)ch*36864 + ocb*2048;
        for(int e=t; e<2304; e+=256){
            int kk = e>>8, rem = e&255;
            cpa(wb_u + (unsigned)(buf*36864 + kk*4096 + rem*16),
                wsrc + kk*4096 + rem*8, 16);
        }
        CP_COMMIT;
    };

    stage(0, 0);
    for(int ch=0; ch<16; ch++){
        int cur = ch & 1;
        CP_WAIT0;
        __syncthreads();
        if(ch < 15) stage(ch+1, 1-cur);
        const char* in_s = smc + cur*16896;
        const char* w_s  = smc + 2*16896 + cur*36864;
        #pragma unroll
        for(int kk=0; kk<9; kk++){
            int ky = kk/3, kx = kk - ky*3;
            uint2 a[2][2];
            #pragma unroll
            for(int mt=0; mt<2; mt++){
                int px0 = px_base + mt*16 + q;
                a[mt][0] = *(const uint2*)(in_s + (((px0>>6)+ky)*66 + (px0&63)+kx)*32 + 8*c);
                int px1 = px0 + 8;
                a[mt][1] = *(const uint2*)(in_s + (((px1>>6)+ky)*66 + (px1&63)+kx)*32 + 8*c);
            }
            const char* wb = w_s + kk*4096 + q*32 + 8*c + wn*64*32;
            #pragma unroll
            for(int nt=0; nt<8; nt++){
                uint2 b = *(const uint2*)(wb + nt*256);
                mma16(acc[0][nt], a[0][0], a[0][1], b);
                mma16(acc[1][nt], a[1][0], a[1][1], b);
            }
        }
        __syncthreads();
    }

    int o_base = ocb*128 + wn*64;
    #pragma unroll
    for(int nt=0; nt<8; nt++){
        int oc = o_base + nt*8 + 2*c;
        float2 bb = *(const float2*)&bias[oc];
        int C = oc >> 4;
        int pos = ipos16(oc & 15);
        #pragma unroll
        for(int mt=0; mt<2; mt++){
            #pragma unroll
            for(int half=0; half<2; half++){
                int px = px_base + mt*16 + q + half*8;
                int y = y0 + (px>>6), x = px&63;
                int row = pb*R2 + y*64 + x;
                float v0 = fmaxf(acc[mt][nt][half*2+0]+bb.x, 0.f);
                float v1 = fmaxf(acc[mt][nt][half*2+1]+bb.y, 0.f);
                if(permout){
                    *(__half2*)&out[(size_t)row*FD + C*16 + pos] = __floats2half2_rn(v0, v1);
                } else {
                    *(__half2*)&out[(size_t)row*FD + oc] = __floats2half2_rn(v0, v1);
                }
            }
        }
    }
}

// ---------------- bilinear grid sample over 3 planes (fp16 features), accumulate ----------------
__global__ void k_sample(const float* __restrict__ query, float* __restrict__ out){
    int gid = blockIdx.x*256 + threadIdx.x;
    int w = gid >> 5, lane = gid & 31;
    if(w >= BN) return;
    int b = w / NP;
    float q0 = query[w*3+0], q1 = query[w*3+1], q2 = query[w*3+2];
    float acc[8] = {0,0,0,0,0,0,0,0};
    #pragma unroll
    for(int pl=0; pl<3; pl++){
        float qa = (pl==2) ? q1 : q0;
        float qb = (pl==1) ? q1 : q2;
        float gx = qa*2.0f - 1.0f, gy = qb*2.0f - 1.0f;
        float x = ((gx + 1.0f)*64.0f - 1.0f)*0.5f;
        float y = ((gy + 1.0f)*64.0f - 1.0f)*0.5f;
        x = fminf(fmaxf(x, 0.0f), 63.0f);
        y = fminf(fmaxf(y, 0.0f), 63.0f);
        float x0f = floorf(x), y0f = floorf(y);
        int x0 = (int)x0f, y0 = (int)y0f;
        int x1 = min(x0+1, 63), y1 = min(y0+1, 63);
        float wx = x - x0f, wy = y - y0f;
        const __half* f = g_fec + (size_t)(pl*BATCH + b)*R2*FD;
        float ww[4] = {(1.f-wx)*(1.f-wy), wx*(1.f-wy), (1.f-wx)*wy, wx*wy};
        int pix[4] = {y0*64+x0, y0*64+x1, y1*64+x0, y1*64+x1};
        #pragma unroll
        for(int tp=0; tp<4; tp++){
            const __half* base = f + pix[tp]*FD + lane*8;
            uint4 v = *(const uint4*)base;
            float g = ww[tp];
            float2 p0 = __half22float2(*(__half2*)&v.x);
            float2 p1 = __half22float2(*(__half2*)&v.y);
            float2 p2 = __half22float2(*(__half2*)&v.z);
            float2 p3 = __half22float2(*(__half2*)&v.w);
            acc[0]+=g*p0.x; acc[1]+=g*p0.y; acc[2]+=g*p1.x; acc[3]+=g*p1.y;
            acc[4]+=g*p2.x; acc[5]+=g*p2.y; acc[6]+=g*p3.x; acc[7]+=g*p3.y;
        }
    }
    float* ob = &out[w*FD + lane*8];
    *(float4*)&ob[0] = make_float4(acc[0],acc[1],acc[2],acc[3]);
    *(float4*)&ob[4] = make_float4(acc[4],acc[5],acc[6],acc[7]);
}

// ---------------- launch ----------------
extern "C" void kernel_launch(void* const* d_in, const int* in_sizes, int n_in,
                              void* d_out, int out_size)
{
    const float* p    = (const float*)d_in[0];
    const float* qry  = (const float*)d_in[1];
    const float* fcW  = (const float*)d_in[2];
    const float* fcb  = (const float*)d_in[3];
    const float* W0   = (const float*)d_in[4];
    const float* b0   = (const float*)d_in[5];
    const float* W1   = (const float*)d_in[6];
    const float* b1   = (const float*)d_in[7];
    const float* Ws   = (const float*)d_in[8];
    const float* Wc   = (const float*)d_in[9];
    const float* bc   = (const float*)d_in[10];
    const float* C1W  = (const float*)d_in[11];
    const float* C1b  = (const float*)d_in[12];
    const float* C2W  = (const float*)d_in[13];
    const float* C2b  = (const float*)d_in[14];
    float* out = (float*)d_out;

    cudaFuncSetAttribute(k_block,    cudaFuncAttributeMaxDynamicSharedMemorySize, SM_BLOCK);
    cudaFuncSetAttribute(k_fcc_bins, cudaFuncAttributeMaxDynamicSharedMemorySize, SM_FCC);
    cudaFuncSetAttribute(k_conv,     cudaFuncAttributeMaxDynamicSharedMemorySize, SM_CONV);

    void *zeros_p, *fea_p, *feb_p, *fec_p, *wt_p;
    cudaGetSymbolAddress(&zeros_p, g_zeros);
    cudaGetSymbolAddress(&fea_p,   g_fea);
    cudaGetSymbolAddress(&feb_p,   g_feb);
    cudaGetSymbolAddress(&fec_p,   g_fec);
    cudaGetSymbolAddress(&wt_p,    g_wt);

    cudaMemsetAsync(zeros_p, 0, (size_t)ZFLOATS*4);
    k_prep<<<(PREP_TOTAL+255)/256, 256>>>(p, W0, W1, Ws, Wc, C1W, C2W);

    k_block<<<BATCH*NT, 256, SM_BLOCK>>>(0, p, fcW, fcb, b0, b1);
    k_block<<<BATCH*NT, 256, SM_BLOCK>>>(1, p, fcW, fcb, b0 + HID, b1 + HID);
    k_block<<<BATCH*NT, 256, SM_BLOCK>>>(2, p, fcW, fcb, b0 + 2*HID, b1 + 2*HID);

    k_fcc_bins<<<NBROW/64, 256, SM_FCC>>>(bc);

    k_conv<<<12*32*2, 256, SM_CONV>>>((const __half*)fea_p, (__half*)feb_p,
                                      (const __half*)wt_p,          C1b, 1);
    k_conv<<<12*32*2, 256, SM_CONV>>>((const __half*)feb_p, (__half*)fec_p,
                                      (const __half*)wt_p + 589824, C2b, 0);

    k_sample<<<(BN*32)/256, 256>>>(qry, out);
}